// round 5
// baseline (speedup 1.0000x reference)
#include <cuda_runtime.h>
#include <math.h>

#define BN_EPS 1e-5f

// ---------------- scratch (static device globals; no allocations) ----------------
__device__ float g_ybuf[16*1024*16*64];   // carve: [0..2M) s0-y / ymax+ymin ; [2M..) part
__device__ float g_h0[16*4096*32];
__device__ float g_p1[16*1024*3];
__device__ float g_h1[16*1024*64];
__device__ float g_p2[16*256*3];
__device__ float g_h2[16*256*128];
__device__ float g_p3[16*64*3];
__device__ float g_h3[16*64*256];
__device__ float g_p4[16*16*3];
__device__ float g_h4[16*16*512];
__device__ int   g_knn1[16*1024*16];
__device__ int   g_knn2[16*256*16];
__device__ int   g_knn3[16*64*16];
__device__ int   g_knn4[16*16*16];
__device__ float g_mid[1024*64];          // s0 per-block channel partials
__device__ float g_mid2[64*1024];         // stats per-block partials (NR=64 x 2D<=1024)
__device__ float g_scale[512];
__device__ float g_shift[512];
__device__ unsigned g_ctr[8];             // zero-init; self-resetting

// ================= FPS segment: T threads, 1 barrier per step =================
template<int N, int T>
__device__ __forceinline__ void fps_seg(const float* __restrict__ p, int M,
                                        float* __restrict__ newp, int b) {
    constexpr int NPT = (N + T - 1) / T;
    constexpr int NW  = T / 32;
    const int tid = threadIdx.x;
    const float* pb = p + (size_t)b * N * 3;
    float lx[NPT], ly[NPT], lz[NPT], md[NPT];
#pragma unroll
    for (int j = 0; j < NPT; j++) {
        int g = j * T + tid;
        if (g < N) { lx[j]=pb[g*3]; ly[j]=pb[g*3+1]; lz[j]=pb[g*3+2]; md[j]=INFINITY; }
        else       { lx[j]=0.f; ly[j]=0.f; lz[j]=0.f; md[j]=-1.f; }
    }
    __shared__ unsigned s_wd[2][NW];
    __shared__ int      s_wi[2][NW];
    if (tid == 0) {
        float* o = newp + (size_t)b * M * 3;
        o[0]=pb[0]; o[1]=pb[1]; o[2]=pb[2];
    }
    float bx = pb[0], by = pb[1], bz = pb[2];
    for (int t = 1; t < M; t++) {
        float best = -0.5f; int besti = 0x7fffffff;
#pragma unroll
        for (int j = 0; j < NPT; j++) {
            float dx = lx[j]-bx, dy = ly[j]-by, dz = lz[j]-bz;
            float d  = fmaf(dx,dx,fmaf(dy,dy,dz*dz));
            float v  = fminf(md[j], d);
            md[j] = v;
            int g = j * T + tid;
            if (v > best || (v == best && g < besti)) { best = v; besti = g; }
        }
        unsigned bb = (best < 0.f) ? 0u : __float_as_uint(best);   // dists >= 0: bits order-preserving
        unsigned mb = __reduce_max_sync(0xffffffffu, bb);
        int cand = (bb == mb) ? besti : 0x7fffffff;
        int wi = __reduce_min_sync(0xffffffffu, cand);
        const int pr = t & 1;
        if ((tid & 31) == 0) { s_wd[pr][tid>>5] = mb; s_wi[pr][tid>>5] = wi; }
        __syncthreads();
        unsigned m2 = 0; int win = 0x7fffffff;
#pragma unroll
        for (int w = 0; w < NW; w++) {
            unsigned u = s_wd[pr][w]; int ii = s_wi[pr][w];
            if (u > m2 || (u == m2 && ii < win)) { m2 = u; win = ii; }
        }
        const float* wp = pb + (size_t)win * 3;   // uniform address, L1-hot
        bx = wp[0]; by = wp[1]; bz = wp[2];
        if (tid == 0) {
            float* o = newp + ((size_t)b * M + t) * 3;
            o[0]=bx; o[1]=by; o[2]=bz;
        }
    }
}

// ============ kNN segment: 256 thr, 4 queries/block, 1 BAR/round ============
__device__ __forceinline__ void knn_seg(const float* __restrict__ p, const float* __restrict__ newp,
                                        int N, int M, int* __restrict__ knnidx,
                                        int blk, float* dist) {
    __shared__ float s_tmin[2][256];
    __shared__ int   s_tidx[2][256];
    const int tid = threadIdx.x;
    const int q0 = blk * 4;
    for (int qq = 0; qq < 4; qq++) {
        const int q = q0 + qq;
        const int b = q / M;
        const float* pb = p + (size_t)b * N * 3;
        const float qx = newp[q*3+0], qy = newp[q*3+1], qz = newp[q*3+2];
        __syncthreads();                       // dist WAR vs previous query
        float bd = INFINITY; int bi = 0x7fffffff;
        for (int n = tid; n < N; n += 256) {
            float dx=qx-pb[n*3], dy=qy-pb[n*3+1], dz=qz-pb[n*3+2];
            float d = fmaf(dx,dx,fmaf(dy,dy,dz*dz));
            dist[n] = d;
            if (d < bd) { bd = d; bi = n; }
        }
        int pr = 0;
        s_tmin[0][tid] = bd; s_tidx[0][tid] = bi;
        __syncthreads();
        for (int r = 0; r < 16; r++) {
            const int lane = tid & 31;
            float m0 = INFINITY; int i0 = 0x7fffffff;
#pragma unroll
            for (int w = 0; w < 8; w++) {      // every warp redundantly reduces all 256 entries
                float mm = s_tmin[pr][lane + 32*w]; int ii = s_tidx[pr][lane + 32*w];
                if (mm < m0 || (mm == m0 && ii < i0)) { m0 = mm; i0 = ii; }
            }
            unsigned b0 = __float_as_uint(m0);
            unsigned mb = __reduce_min_sync(0xffffffffu, b0);
            int cand = (b0 == mb) ? i0 : 0x7fffffff;
            int win = __reduce_min_sync(0xffffffffu, cand);
            if (tid == 0) knnidx[(size_t)q*16 + r] = win;
            if (r == 15) break;
            float nb = s_tmin[pr][tid]; int ni = s_tidx[pr][tid];
            if ((win & 255) == tid) {          // owner rescans its slice
                dist[win] = INFINITY;
                nb = INFINITY; ni = 0x7fffffff;
                for (int n = tid; n < N; n += 256) {
                    float d = dist[n];
                    if (d < nb) { nb = d; ni = n; }
                }
            }
            s_tmin[pr^1][tid] = nb; s_tidx[pr^1][tid] = ni;   // double-buffer copy
            pr ^= 1;
            __syncthreads();
        }
    }
}

// ====== grouped GEMM segment: fused max/min over k + block-level stats ======
template<int C, int D>
__device__ __forceinline__ void gemm_seg(const float* __restrict__ p, const float* __restrict__ h,
                                         const float* __restrict__ newp, const int* __restrict__ knnidx,
                                         const float* __restrict__ W, int N, int M,
                                         float* __restrict__ ymax, float* __restrict__ ymin,
                                         float* __restrict__ part, int blk, float* feat) {
    constexpr int F   = C + 3;
    constexpr int QPB = (D >= 256) ? 1 : (256 / D);
    constexpr int CPT = (D + 255) / 256;
    __shared__ int   s_knn[QPB*16];
    __shared__ float s_np[QPB*3];
    __shared__ float s_red[256];
    const int t  = threadIdx.x;
    const int q0 = blk * QPB;
    const int b  = q0 / M;
    if (t < QPB*16) s_knn[t] = knnidx[(size_t)q0*16 + t];
    if (t < QPB*3)  s_np[t]  = newp[q0*3 + t];
    __syncthreads();
    const float* pb = p + (size_t)b * N * 3;
    const float* hb = h + (size_t)b * N * C;
    for (int e = t; e < QPB*16*F; e += 256) {
        int qi = e / (16*F);
        int rem = e - qi*16*F;
        int k = rem / F, c = rem - k*F;
        int n = s_knn[qi*16 + k];
        feat[e] = (c < 3) ? (pb[n*3+c] - s_np[qi*3+c]) : hb[(size_t)n*C + (c-3)];
    }
    __syncthreads();
    const int qi = t / D;
    const int d  = t - qi*D;
    const float* fq = feat + qi*16*F;
    float acc[16*CPT];
#pragma unroll
    for (int i = 0; i < 16*CPT; i++) acc[i] = 0.f;
    for (int c = 0; c < F; c++) {
        float w0 = W[(size_t)c*D + d];
        float w1 = (CPT == 2) ? W[(size_t)c*D + d + 256] : 0.f;
#pragma unroll
        for (int k = 0; k < 16; k++) {
            float fv = fq[k*F + c];
            acc[k] = fmaf(fv, w0, acc[k]);
            if (CPT == 2) acc[16+k] = fmaf(fv, w1, acc[16+k]);
        }
    }
    const int q = q0 + qi;
    float ssum = 0.f, ssq = 0.f;
#pragma unroll
    for (int cc = 0; cc < CPT; cc++) {
        float mx = -INFINITY, mn = INFINITY, s = 0.f, s2 = 0.f;
#pragma unroll
        for (int k = 0; k < 16; k++) {
            float v = acc[cc*16 + k];
            mx = fmaxf(mx, v); mn = fminf(mn, v);
            s += v; s2 = fmaf(v, v, s2);
        }
        int dd = d + cc*256;
        ymax[(size_t)q*D + dd] = mx;
        ymin[(size_t)q*D + dd] = mn;
        if (QPB == 1) {
            part[(size_t)blk*2*D + dd]     = s;
            part[(size_t)blk*2*D + D + dd] = s2;
        } else { ssum = s; ssq = s2; }
    }
    if (QPB > 1) {       // deterministic in-block reduce over QPB queries
        s_red[t] = ssum;
        __syncthreads();
        float tot = 0.f;
        if (t < D) { for (int q2 = 0; q2 < QPB; q2++) tot += s_red[t + q2*D]; }
        __syncthreads();
        s_red[t] = ssq;
        __syncthreads();
        if (t < D) {
            float tot2 = 0.f;
            for (int q2 = 0; q2 < QPB; q2++) tot2 += s_red[t + q2*D];
            part[(size_t)blk*2*D + t]     = tot;
            part[(size_t)blk*2*D + D + t] = tot2;
        }
    }
}

// ====== stats: 2-level reduce with counter-elected finalize (deterministic) ======
__device__ __forceinline__ void statsf_seg(const float* __restrict__ part, int R, int D, float cnt,
                                           const float* __restrict__ g, const float* __restrict__ bta,
                                           float* __restrict__ scale, float* __restrict__ shift,
                                           float* __restrict__ mid2, unsigned* ctr, int blk, int NR) {
    const int t = threadIdx.x;
    const int per = (R + NR - 1) / NR;
    const int r0 = blk * per;
    const int r1 = min(r0 + per, R);
    for (int c = t; c < 2*D; c += 256) {
        float s = 0.f;
        for (int r = r0; r < r1; r++) s += part[(size_t)r*2*D + c];
        mid2[(size_t)blk*2*D + c] = s;
    }
    __threadfence();
    __shared__ unsigned s_old;
    __syncthreads();
    if (t == 0) s_old = atomicAdd(ctr, 1u);
    __syncthreads();
    if (s_old == (unsigned)(NR - 1)) {
        __threadfence();
        for (int c = t; c < D; c += 256) {
            float S = 0.f, Q2 = 0.f;
            for (int i = 0; i < NR; i++) {
                S  += mid2[(size_t)i*2*D + c];
                Q2 += mid2[(size_t)i*2*D + D + c];
            }
            float m = S / cnt;
            float v = Q2 / cnt - m*m;
            float sc = g[c] * rsqrtf(v + BN_EPS);
            scale[c] = sc;
            shift[c] = bta[c] - m*sc;
        }
        if (t == 0) *ctr = 0;
    }
}

// ====== stage0: y = x@W1 fused with counter-finalized stats (512 threads) ======
__device__ __forceinline__ void s0_seg(const float* __restrict__ x, const float* __restrict__ W1,
                                       const float* __restrict__ g1, const float* __restrict__ b1,
                                       float* __restrict__ y, float* __restrict__ mid,
                                       float* __restrict__ scale, float* __restrict__ shift,
                                       unsigned* ctr, int blk) {
    const int t = threadIdx.x;
    const int c = t & 31;
    float w0 = W1[c], w1 = W1[32+c], w2 = W1[64+c];
    const int base = blk * 2048;
    float s = 0.f, s2 = 0.f;
#pragma unroll
    for (int j = 0; j < 4; j++) {
        int e = base + t + 512*j;                     // channel = t&31 (512,2048 % 32 == 0)
        int pt = e >> 5;
        const float* xp = x + (size_t)pt*3;
        float v = fmaf(xp[0], w0, fmaf(xp[1], w1, xp[2]*w2));
        y[e] = v;
        s += v; s2 = fmaf(v, v, s2);
    }
    __shared__ float rs[512], rq[512];
    rs[t] = s; rq[t] = s2;
    __syncthreads();
    if (t < 32) {
        float S = 0.f, Q = 0.f;
#pragma unroll
        for (int gr = 0; gr < 16; gr++) { S += rs[t + 32*gr]; Q += rq[t + 32*gr]; }
        mid[(size_t)blk*64 + t]      = S;
        mid[(size_t)blk*64 + 32 + t] = Q;
    }
    __threadfence();
    __shared__ unsigned s_old;
    __syncthreads();
    if (t == 0) s_old = atomicAdd(ctr, 1u);
    __syncthreads();
    if (s_old == 1023u) {
        __threadfence();
        const int col = t & 63, grp = t >> 6;         // 8 row-groups
        float S = 0.f;
        for (int r = grp; r < 1024; r += 8) S += mid[(size_t)r*64 + col];
        __syncthreads();                               // reuse rs
        rs[t] = S;
        __syncthreads();
        if (t < 64) {
            float T2 = 0.f;
#pragma unroll
            for (int gg = 0; gg < 8; gg++) T2 += rs[gg*64 + t];
            rq[t] = T2;                                // [0..32)=sum, [32..64)=sumsq
        }
        __syncthreads();
        if (t < 32) {
            float m = rq[t] * (1.f/65536.f);           // 16*4096 samples/channel
            float v = rq[32+t] * (1.f/65536.f) - m*m;
            float sc = g1[t] * rsqrtf(v + BN_EPS);
            scale[t] = sc;
            shift[t] = b1[t] - m*sc;
        }
        if (t == 0) *ctr = 0;
    }
}

// ====== elementwise normalize segments (4 elems/thread) ======
__device__ __forceinline__ void norm0_seg(const float* __restrict__ y, const float* __restrict__ scale,
                                          const float* __restrict__ shift, int total,
                                          float* __restrict__ out, int blk) {
    int base = blk*1024 + threadIdx.x;
#pragma unroll
    for (int j = 0; j < 4; j++) {
        int i = base + 256*j;
        if (i < total) {
            int c = i & 31;
            out[i] = fmaxf(0.f, fmaf(y[i], scale[c], shift[c]));
        }
    }
}
__device__ __forceinline__ void tdnorm_seg(const float* __restrict__ ymax, const float* __restrict__ ymin,
                                           const float* __restrict__ scale, const float* __restrict__ shift,
                                           int total, int Dmask, float* __restrict__ out, int blk) {
    int base = blk*1024 + threadIdx.x;
#pragma unroll
    for (int j = 0; j < 4; j++) {
        int i = base + 256*j;
        if (i < total) {
            int c = i & Dmask;
            float sc = scale[c];
            float v = (sc >= 0.f) ? ymax[i] : ymin[i];
            out[i] = fmaxf(0.f, fmaf(v, sc, shift[c]));
        }
    }
}

// ================= fat launch wrappers =================
__global__ __launch_bounds__(512) void kA(const float* x, const float* W1, const float* g1, const float* b1,
                                          float* y, float* mid, float* scale, float* shift, unsigned* ctr,
                                          float* p1) {
    if (blockIdx.x < 16) fps_seg<4096,512>(x, 1024, p1, blockIdx.x);
    else s0_seg(x, W1, g1, b1, y, mid, scale, shift, ctr, blockIdx.x - 16);
}

__global__ __launch_bounds__(256) void kB(const float* x, const float* p1, float* p2, int* knn1,
                                          const float* y, const float* scale, const float* shift, float* h0) {
    extern __shared__ float dyn[];
    int bx = blockIdx.x;
    if (bx < 16) fps_seg<1024,256>(p1, 256, p2, bx);
    else if (bx < 16 + 4096) knn_seg(x, p1, 4096, 1024, knn1, bx - 16, dyn);
    else norm0_seg(y, scale, shift, 16*4096*32, h0, bx - 16 - 4096);
}

__global__ __launch_bounds__(256) void kC(const float* x, const float* h0, const float* p1, const float* p2,
                                          float* p3, const int* knn1, int* knn2, const float* W2,
                                          float* ymax, float* ymin, float* part) {
    extern __shared__ float dyn[];
    int bx = blockIdx.x;
    if (bx < 16) fps_seg<256,256>(p2, 64, p3, bx);
    else if (bx < 16 + 4096) gemm_seg<32,64>(x, h0, p1, knn1, W2, 4096, 1024, ymax, ymin, part, bx - 16, dyn);
    else knn_seg(p1, p2, 1024, 256, knn2, bx - 16 - 4096, dyn);
}

__global__ __launch_bounds__(256) void kD(const float* p2, const float* p3, float* p4, int* knn3,
                                          const float* part, const float* g2, const float* b2,
                                          float* scale, float* shift, float* mid2, unsigned* ctr) {
    extern __shared__ float dyn[];
    int bx = blockIdx.x;
    if (bx < 16) fps_seg<64,256>(p3, 16, p4, bx);
    else if (bx < 16 + 64) statsf_seg(part, 4096, 64, (float)(16*1024*16), g2, b2, scale, shift, mid2, ctr, bx - 16, 64);
    else knn_seg(p2, p3, 256, 64, knn3, bx - 16 - 64, dyn);
}

__global__ __launch_bounds__(256) void kE(const float* ymax, const float* ymin, const float* scale,
                                          const float* shift, float* h1,
                                          const float* p3, const float* p4, int* knn4) {
    extern __shared__ float dyn[];
    int bx = blockIdx.x;
    if (bx < 1024) tdnorm_seg(ymax, ymin, scale, shift, 16*1024*64, 63, h1, bx);
    else knn_seg(p3, p4, 64, 16, knn4, bx - 1024, dyn);
}

__global__ __launch_bounds__(256) void kGemm2(const float* p1, const float* h1, const float* p2,
                                              const int* knn2, const float* W3,
                                              float* ymax, float* ymin, float* part) {
    extern __shared__ float dyn[];
    gemm_seg<64,128>(p1, h1, p2, knn2, W3, 1024, 256, ymax, ymin, part, blockIdx.x, dyn);
}
__global__ __launch_bounds__(256) void kGemm3(const float* p2, const float* h2, const float* p3,
                                              const int* knn3, const float* W4,
                                              float* ymax, float* ymin, float* part) {
    extern __shared__ float dyn[];
    gemm_seg<128,256>(p2, h2, p3, knn3, W4, 256, 64, ymax, ymin, part, blockIdx.x, dyn);
}
__global__ __launch_bounds__(256) void kGemm4(const float* p3, const float* h3, const float* p4,
                                              const int* knn4, const float* W5,
                                              float* ymax, float* ymin, float* part) {
    extern __shared__ float dyn[];
    gemm_seg<256,512>(p3, h3, p4, knn4, W5, 64, 16, ymax, ymin, part, blockIdx.x, dyn);
}

__global__ __launch_bounds__(256) void kStats(const float* part, int R, int D, float cnt,
                                              const float* g, const float* bta,
                                              float* scale, float* shift, float* mid2, unsigned* ctr) {
    statsf_seg(part, R, D, cnt, g, bta, scale, shift, mid2, ctr, blockIdx.x, 64);
}

__global__ __launch_bounds__(256) void kNorm(const float* ymax, const float* ymin, const float* scale,
                                             const float* shift, int total, int Dmask, float* out) {
    tdnorm_seg(ymax, ymin, scale, shift, total, Dmask, out, blockIdx.x);
}

// ---------------- classifier head: single block, channel-per-thread ----------------
__global__ __launch_bounds__(256) void classifier_kernel(const float* __restrict__ h4,
                                  const float* __restrict__ Wc1, const float* __restrict__ bc1,
                                  const float* __restrict__ gc1, const float* __restrict__ hc1,
                                  const float* __restrict__ Wc2, const float* __restrict__ bc2,
                                  const float* __restrict__ gc2, const float* __restrict__ hc2,
                                  const float* __restrict__ Wc3, const float* __restrict__ bc3,
                                  float* __restrict__ out) {
    __shared__ float sb[12288];
    float* z  = sb;
    float* z1 = sb + 8192;
    const int t = threadIdx.x;
    for (int e = t; e < 8192; e += 256) {
        int b = e >> 9, c = e & 511;
        float s = 0.f;
        for (int k = 0; k < 16; k++) s += h4[((size_t)(b*16 + k))*512 + c];
        z[e] = s * (1.f/16.f);
    }
    __syncthreads();
    {
        float acc[16];
#pragma unroll
        for (int b = 0; b < 16; b++) acc[b] = bc1[t];
        for (int i = 0; i < 512; i++) {
            float w = Wc1[(size_t)i*256 + t];
#pragma unroll
            for (int b = 0; b < 16; b++) acc[b] = fmaf(z[b*512 + i], w, acc[b]);
        }
        float m = 0.f;
#pragma unroll
        for (int b = 0; b < 16; b++) m += acc[b];
        m *= (1.f/16.f);
        float v = 0.f;
#pragma unroll
        for (int b = 0; b < 16; b++) { float d = acc[b]-m; v = fmaf(d,d,v); }
        v *= (1.f/16.f);
        float sc = gc1[t] * rsqrtf(v + BN_EPS);
        float sh = hc1[t] - m * sc;
#pragma unroll
        for (int b = 0; b < 16; b++) z1[b*256 + t] = fmaxf(0.f, fmaf(acc[b], sc, sh));
    }
    __syncthreads();
    float* z2 = sb;
    if (t < 128) {
        float acc[16];
#pragma unroll
        for (int b = 0; b < 16; b++) acc[b] = bc2[t];
        for (int i = 0; i < 256; i++) {
            float w = Wc2[(size_t)i*128 + t];
#pragma unroll
            for (int b = 0; b < 16; b++) acc[b] = fmaf(z1[b*256 + i], w, acc[b]);
        }
        float m = 0.f;
#pragma unroll
        for (int b = 0; b < 16; b++) m += acc[b];
        m *= (1.f/16.f);
        float v = 0.f;
#pragma unroll
        for (int b = 0; b < 16; b++) { float d = acc[b]-m; v = fmaf(d,d,v); }
        v *= (1.f/16.f);
        float sc = gc2[t] * rsqrtf(v + BN_EPS);
        float sh = hc2[t] - m * sc;
#pragma unroll
        for (int b = 0; b < 16; b++) z2[b*128 + t] = fmaxf(0.f, fmaf(acc[b], sc, sh));
    }
    __syncthreads();
    if (t < 40) {
        float acc[16];
#pragma unroll
        for (int b = 0; b < 16; b++) acc[b] = bc3[t];
        for (int i = 0; i < 128; i++) {
            float w = Wc3[(size_t)i*40 + t];
#pragma unroll
            for (int b = 0; b < 16; b++) acc[b] = fmaf(z2[b*128 + i], w, acc[b]);
        }
#pragma unroll
        for (int b = 0; b < 16; b++) out[b*40 + t] = acc[b];
    }
}

// ---------------- driver ----------------
extern "C" void kernel_launch(void* const* d_in, const int* in_sizes, int n_in,
                              void* d_out, int out_size) {
    (void)in_sizes; (void)n_in; (void)out_size;
    const float* x   = (const float*)d_in[0];
    const float* W1  = (const float*)d_in[1];
    const float* g1  = (const float*)d_in[2];
    const float* b1  = (const float*)d_in[3];
    const float* W2  = (const float*)d_in[4];
    const float* g2  = (const float*)d_in[5];
    const float* b2  = (const float*)d_in[6];
    const float* W3  = (const float*)d_in[7];
    const float* g3  = (const float*)d_in[8];
    const float* b3  = (const float*)d_in[9];
    const float* W4  = (const float*)d_in[10];
    const float* g4  = (const float*)d_in[11];
    const float* b4  = (const float*)d_in[12];
    const float* W5  = (const float*)d_in[13];
    const float* g5  = (const float*)d_in[14];
    const float* b5  = (const float*)d_in[15];
    const float* Wc1 = (const float*)d_in[16];
    const float* bc1 = (const float*)d_in[17];
    const float* gc1 = (const float*)d_in[18];
    const float* hc1 = (const float*)d_in[19];
    const float* Wc2 = (const float*)d_in[20];
    const float* bc2 = (const float*)d_in[21];
    const float* gc2 = (const float*)d_in[22];
    const float* hc2 = (const float*)d_in[23];
    const float* Wc3 = (const float*)d_in[24];
    const float* bc3 = (const float*)d_in[25];
    float* out = (float*)d_out;

    float *ybuf, *h0, *p1, *h1, *p2, *h2, *p3, *h3, *p4, *h4, *mid, *mid2, *scale, *shift;
    int *kn1, *kn2, *kn3, *kn4;
    unsigned* ctr;
    cudaGetSymbolAddress((void**)&ybuf,  g_ybuf);
    cudaGetSymbolAddress((void**)&h0,    g_h0);
    cudaGetSymbolAddress((void**)&p1,    g_p1);
    cudaGetSymbolAddress((void**)&h1,    g_h1);
    cudaGetSymbolAddress((void**)&p2,    g_p2);
    cudaGetSymbolAddress((void**)&h2,    g_h2);
    cudaGetSymbolAddress((void**)&p3,    g_p3);
    cudaGetSymbolAddress((void**)&h3,    g_h3);
    cudaGetSymbolAddress((void**)&p4,    g_p4);
    cudaGetSymbolAddress((void**)&h4,    g_h4);
    cudaGetSymbolAddress((void**)&kn1,   g_knn1);
    cudaGetSymbolAddress((void**)&kn2,   g_knn2);
    cudaGetSymbolAddress((void**)&kn3,   g_knn3);
    cudaGetSymbolAddress((void**)&kn4,   g_knn4);
    cudaGetSymbolAddress((void**)&mid,   g_mid);
    cudaGetSymbolAddress((void**)&mid2,  g_mid2);
    cudaGetSymbolAddress((void**)&scale, g_scale);
    cudaGetSymbolAddress((void**)&shift, g_shift);
    cudaGetSymbolAddress((void**)&ctr,   g_ctr);

    // carve from ybuf: [0..1M) ymax, [1M..2M) ymin, [2M..) part.
    // stage0's raw y also uses [0..2M): dead after kB (norm0) before gemm1 writes in kC.
    float* ymax = ybuf;
    float* ymin = ybuf + 1048576;
    float* part = ybuf + 2097152;

    // A: fps1 || s0(+fused stats)
    kA<<<16 + 1024, 512>>>(x, W1, g1, b1, ybuf, mid, scale, shift, ctr, p1);
    // B: fps2 || knn1 || norm0
    kB<<<16 + 4096 + 2048, 256, 4096*4>>>(x, p1, p2, kn1, ybuf, scale, shift, h0);
    // C: fps3 || gemm1 || knn2
    kC<<<16 + 4096 + 1024, 256, 4*16*35*4>>>(x, h0, p1, p2, p3, kn1, kn2, W2, ymax, ymin, part);
    // D: fps4 || stats1 || knn3
    kD<<<16 + 64 + 256, 256, 256*4>>>(p2, p3, p4, kn3, part, g2, b2, scale, shift, mid2, ctr + 1);
    // E: norm1 || knn4
    kE<<<1024 + 64, 256, 64*4>>>(ymax, ymin, scale, shift, h1, p3, p4, kn4);
    // F..: serial tail
    kGemm2<<<2048, 256, 2*16*67*4>>>(p1, h1, p2, kn2, W3, ymax, ymin, part);
    kStats<<<64, 256>>>(part, 2048, 128, (float)(16*256*16), g3, b3, scale, shift, mid2, ctr + 2);
    kNorm<<<512, 256>>>(ymax, ymin, scale, shift, 16*256*128, 127, h2);
    kGemm3<<<1024, 256, 16*131*4>>>(p2, h2, p3, kn3, W4, ymax, ymin, part);
    kStats<<<64, 256>>>(part, 1024, 256, (float)(16*64*16), g4, b4, scale, shift, mid2, ctr + 3);
    kNorm<<<256, 256>>>(ymax, ymin, scale, shift, 16*64*256, 255, h3);
    kGemm4<<<256, 256, 16*259*4>>>(p3, h3, p4, kn4, W5, ymax, ymin, part);
    kStats<<<64, 256>>>(part, 256, 512, (float)(16*16*16), g5, b5, scale, shift, mid2, ctr + 4);
    kNorm<<<128, 256>>>(ymax, ymin, scale, shift, 16*16*512, 511, h4);
    classifier_kernel<<<1, 256>>>(h4, Wc1, bc1, gc1, hc1, Wc2, bc2, gc2, hc2, Wc3, bc3, out);
}

// round 6
// speedup vs baseline: 1.1309x; 1.1309x over previous
#include <cuda_runtime.h>
#include <math.h>

#define BN_EPS 1e-5f

// ---------------- scratch (static device globals; no allocations) ----------------
__device__ float g_ybuf[16*1024*16*64];   // carved: stage0 ybuf | ymax | ymin | part | part2
__device__ float g_h0[16*4096*32];
__device__ float g_p1[16*1024*3];
__device__ float g_h1[16*1024*64];
__device__ float g_p2[16*256*3];
__device__ float g_h2[16*256*128];
__device__ float g_p3[16*64*3];
__device__ float g_h3[16*64*256];
__device__ float g_p4[16*16*3];
__device__ float g_h4[16*16*512];
__device__ int   g_knn[16*1024*16];
__device__ float g_part[512*2*512];       // stage0 partials [NB][2][D]
__device__ float g_scale[512];
__device__ float g_shift[512];

// ---------------- FPS: one block per batch, registers + 1 barrier per step ----------------
template<int N, int T>
__global__ void fps_kernel(const float* __restrict__ p, int M, float* __restrict__ newp) {
    constexpr int NPT = N / T;
    constexpr int NW  = T / 32;
    const int b = blockIdx.x, tid = threadIdx.x;
    const float* pb = p + (size_t)b * N * 3;
    float lx[NPT], ly[NPT], lz[NPT], md[NPT];
#pragma unroll
    for (int j = 0; j < NPT; j++) {
        int g = j * T + tid;
        lx[j] = pb[g*3+0]; ly[j] = pb[g*3+1]; lz[j] = pb[g*3+2];
        md[j] = INFINITY;
    }
    __shared__ unsigned s_wd[2][NW];
    __shared__ int      s_wi[2][NW];
    if (tid == 0) {
        float* o = newp + (size_t)b * M * 3;
        o[0] = pb[0]; o[1] = pb[1]; o[2] = pb[2];
    }
    float bx = pb[0], by = pb[1], bz = pb[2];
    for (int t = 1; t < M; t++) {
        // local min-dist update + argmax (first-index tie-break)
        float best = -0.5f; int besti = 0x7fffffff;
#pragma unroll
        for (int j = 0; j < NPT; j++) {
            float dx = lx[j]-bx, dy = ly[j]-by, dz = lz[j]-bz;
            float d = fmaf(dx, dx, fmaf(dy, dy, dz*dz));
            float v = fminf(md[j], d);
            md[j] = v;
            int g = j * T + tid;
            if (v > best || (v == best && g < besti)) { best = v; besti = g; }
        }
        // warp argmax via REDUX (dists >= 0 so float bits are order-preserving)
        unsigned bb = __float_as_uint(best < 0.f ? 0.f : best);
        unsigned mb = __reduce_max_sync(0xffffffffu, bb);
        int cand = (bb == mb) ? besti : 0x7fffffff;
        int wbi = __reduce_min_sync(0xffffffffu, cand);
        const int pr = t & 1;                    // double buffer -> 1 barrier/step is race-free
        if ((tid & 31) == 0) { s_wd[pr][tid >> 5] = mb; s_wi[pr][tid >> 5] = wbi; }
        __syncthreads();
        // every thread redundantly combines the NW warp winners (removes 2nd barrier)
        unsigned m2 = 0; int win = 0x7fffffff;
#pragma unroll
        for (int w = 0; w < NW; w++) {
            unsigned u = s_wd[pr][w]; int ii = s_wi[pr][w];
            if (u > m2 || (u == m2 && ii < win)) { m2 = u; win = ii; }
        }
        // winner coords: uniform address, L1-hot (48KB point set warmed at init)
        const float* wp = pb + (size_t)win * 3;
        bx = wp[0]; by = wp[1]; bz = wp[2];
        if (tid == 0) {
            float* o = newp + ((size_t)b * M + t) * 3;
            o[0] = bx; o[1] = by; o[2] = bz;
        }
    }
}

// ---------------- kNN: cached per-thread minima, one owner rescan per round ----------------
__global__ void knn_kernel(const float* __restrict__ p, const float* __restrict__ newp,
                           int N, int M, int* __restrict__ knn) {
    extern __shared__ float dist[];          // N floats
    __shared__ float s_tmin[128];
    __shared__ int   s_tidx[128];
    __shared__ int   s_win;
    const int q = blockIdx.x;
    const int b = q / M;
    const int tid = threadIdx.x;
    const float* pb = p + (size_t)b * N * 3;
    const float qx = newp[q*3+0], qy = newp[q*3+1], qz = newp[q*3+2];
    float bd = INFINITY; int bi = 0x7fffffff;
    for (int n = tid; n < N; n += 128) {
        float dx = qx - pb[n*3+0], dy = qy - pb[n*3+1], dz = qz - pb[n*3+2];
        float d = fmaf(dx, dx, fmaf(dy, dy, dz*dz));
        dist[n] = d;
        if (d < bd) { bd = d; bi = n; }      // ascending n -> first-index ties
    }
    s_tmin[tid] = bd; s_tidx[tid] = bi;
    __syncthreads();
    for (int r = 0; ; r++) {
        if (tid < 32) {
            float m0 = s_tmin[tid]; int i0 = s_tidx[tid];
#pragma unroll
            for (int off = 32; off < 128; off += 32) {
                float mm = s_tmin[tid + off]; int ii = s_tidx[tid + off];
                if (mm < m0 || (mm == m0 && ii < i0)) { m0 = mm; i0 = ii; }
            }
            unsigned b0 = __float_as_uint(m0);
            unsigned mb = __reduce_min_sync(0xffffffffu, b0);
            int cand = (b0 == mb) ? i0 : 0x7fffffff;
            int win = __reduce_min_sync(0xffffffffu, cand);
            if (tid == 0) { knn[(size_t)q*16 + r] = win; s_win = win; }
        }
        __syncthreads();
        if (r == 15) break;
        int win = s_win;
        if ((win & 127) == tid) {            // owner rescans its slice
            dist[win] = INFINITY;
            float nb = INFINITY; int ni = 0x7fffffff;
            for (int n = tid; n < N; n += 128) {
                float d = dist[n];
                if (d < nb) { nb = d; ni = n; }
            }
            s_tmin[tid] = nb; s_tidx[tid] = ni;
        }
        __syncthreads();
    }
}

// ---------------- fused grouped GEMM + max/min over k + per-block channel stats ----------------
__global__ void td_gemm_fused(const float* __restrict__ p, const float* __restrict__ h,
                              const float* __restrict__ newp, const int* __restrict__ knn,
                              const float* __restrict__ W, int N, int M, int C, int D,
                              float* __restrict__ ymax, float* __restrict__ ymin,
                              float* __restrict__ part) {
    extern __shared__ float feat[];          // 16*(C+3)
    __shared__ int   s_knn[16];
    __shared__ float s_np[3];
    const int q = blockIdx.x;
    const int b = q / M;
    const int t = threadIdx.x;               // D threads, one per output channel
    if (t < 16) s_knn[t] = knn[(size_t)q*16 + t];
    if (t < 3)  s_np[t]  = newp[q*3 + t];
    __syncthreads();
    const int F = C + 3;
    const float* pb = p + (size_t)b * N * 3;
    const float* hb = h + (size_t)b * N * C;
    for (int e = t; e < 16 * F; e += D) {
        int k = e / F, c = e - k * F;
        int n = s_knn[k];
        feat[e] = (c < 3) ? (pb[n*3 + c] - s_np[c]) : hb[(size_t)n * C + (c - 3)];
    }
    __syncthreads();
    float acc[16];
#pragma unroll
    for (int k = 0; k < 16; k++) acc[k] = 0.f;
#pragma unroll 2
    for (int c = 0; c < F; c++) {
        float w = W[(size_t)c * D + t];      // loaded once per c
#pragma unroll
        for (int k = 0; k < 16; k++) acc[k] = fmaf(feat[k*F + c], w, acc[k]);
    }
    float mx = -INFINITY, mn = INFINITY, s = 0.f, s2 = 0.f;
#pragma unroll
    for (int k = 0; k < 16; k++) {
        float v = acc[k];
        mx = fmaxf(mx, v); mn = fminf(mn, v);
        s += v; s2 = fmaf(v, v, s2);
    }
    ymax[(size_t)q * D + t] = mx;
    ymin[(size_t)q * D + t] = mn;
    part[(size_t)q * 2 * D + t]     = s;
    part[(size_t)q * 2 * D + D + t] = s2;
}

// ---------------- stats tree: level-1 reduce of per-block partials ----------------
__global__ void stats_reduce(const float* __restrict__ part, int Q, int D,
                             float* __restrict__ out) {
    const int t = threadIdx.x;               // D threads
    const int per = (Q + gridDim.x - 1) / gridDim.x;
    const int r0 = blockIdx.x * per;
    const int r1 = min(r0 + per, Q);
    float s = 0.f, s2 = 0.f;
    for (int r = r0; r < r1; r++) {
        s  += part[(size_t)r * 2 * D + t];
        s2 += part[(size_t)r * 2 * D + D + t];
    }
    out[(size_t)blockIdx.x * 2 * D + t]     = s;
    out[(size_t)blockIdx.x * 2 * D + D + t] = s2;
}

__global__ void stats_final(const float* __restrict__ part, int NB, int D, float cnt,
                            const float* __restrict__ g, const float* __restrict__ bta,
                            float* __restrict__ scale, float* __restrict__ shift) {
    const int c = threadIdx.x;
    if (c >= D) return;
    float S = 0.f, Q2 = 0.f;
    for (int i = 0; i < NB; i++) {
        S  += part[(size_t)i * 2 * D + c];
        Q2 += part[(size_t)i * 2 * D + D + c];
    }
    float m = S / cnt;
    float v = Q2 / cnt - m * m;
    float sc = g[c] * rsqrtf(v + BN_EPS);
    scale[c] = sc;
    shift[c] = bta[c] - m * sc;
}

// ---------------- apply BN+ReLU to the sign-appropriate extremum ----------------
__global__ void td_norm(const float* __restrict__ ymax, const float* __restrict__ ymin,
                        const float* __restrict__ scale, const float* __restrict__ shift,
                        int total, int D, float* __restrict__ hout) {
    int i = blockIdx.x * 256 + threadIdx.x;
    if (i >= total) return;
    int d = i % D;
    float sc = scale[d];
    float v = (sc >= 0.f) ? ymax[i] : ymin[i];
    hout[i] = fmaxf(0.f, fmaf(v, sc, shift[d]));
}

// ---------------- stage 0: h = p @ W1 (3->32) ----------------
__global__ void s0_gemm(const float* __restrict__ x, const float* __restrict__ W1,
                        float* __restrict__ y) {
    int i = blockIdx.x * 256 + threadIdx.x;
    if (i >= 16*4096*32) return;
    int pt = i >> 5, c = i & 31;
    const float* xp = x + (size_t)pt * 3;
    y[i] = fmaf(xp[0], W1[c], fmaf(xp[1], W1[32+c], xp[2]*W1[64+c]));
}

__global__ void stats_partial(const float* __restrict__ y, int Q, int D, float* __restrict__ part) {
    const int NB = gridDim.x;
    const int rpb = (Q + NB - 1) / NB;
    const int r0 = blockIdx.x * rpb;
    const int r1 = min(r0 + rpb, Q);
    __shared__ float ss[256], sq[256];
    const int tid = threadIdx.x;
    const int rpi = 256 / D;
    const int c = tid % D;
    const int ro = tid / D;
    float s = 0.f, q2 = 0.f;
    for (int r = r0 + ro; r < r1; r += rpi) {
        float v = y[(size_t)r * D + c]; s += v; q2 = fmaf(v, v, q2);
    }
    ss[tid] = s; sq[tid] = q2;
    __syncthreads();
    if (tid < D) {
        for (int o = 1; o < rpi; o++) { s += ss[tid + o*D]; q2 += sq[tid + o*D]; }
        part[(size_t)blockIdx.x * 2 * D + tid]     = s;
        part[(size_t)blockIdx.x * 2 * D + D + tid] = q2;
    }
}

__global__ void normalize_kernel(const float* __restrict__ y, const float* __restrict__ scale,
                                 const float* __restrict__ shift, int total, int D,
                                 float* __restrict__ out) {
    int i = blockIdx.x * 256 + threadIdx.x;
    if (i >= total) return;
    int c = i % D;
    out[i] = fmaxf(0.f, fmaf(y[i], scale[c], shift[c]));
}

// ---------------- classifier head: single block, channel-per-thread ----------------
__global__ void classifier_kernel(const float* __restrict__ h4,
                                  const float* __restrict__ Wc1, const float* __restrict__ bc1,
                                  const float* __restrict__ gc1, const float* __restrict__ hc1,
                                  const float* __restrict__ Wc2, const float* __restrict__ bc2,
                                  const float* __restrict__ gc2, const float* __restrict__ hc2,
                                  const float* __restrict__ Wc3, const float* __restrict__ bc3,
                                  float* __restrict__ out) {
    __shared__ float sb[12288];
    float* z  = sb;
    float* z1 = sb + 8192;
    const int t = threadIdx.x;  // 256 threads
    for (int e = t; e < 8192; e += 256) {
        int b = e >> 9, c = e & 511;
        float s = 0.f;
        for (int k = 0; k < 16; k++) s += h4[((size_t)(b*16 + k))*512 + c];
        z[e] = s * (1.f/16.f);
    }
    __syncthreads();
    {
        float acc[16];
#pragma unroll
        for (int b = 0; b < 16; b++) acc[b] = bc1[t];
        for (int i = 0; i < 512; i++) {
            float w = Wc1[(size_t)i*256 + t];
#pragma unroll
            for (int b = 0; b < 16; b++) acc[b] = fmaf(z[b*512 + i], w, acc[b]);
        }
        float m = 0.f;
#pragma unroll
        for (int b = 0; b < 16; b++) m += acc[b];
        m *= (1.f/16.f);
        float v = 0.f;
#pragma unroll
        for (int b = 0; b < 16; b++) { float d = acc[b]-m; v = fmaf(d, d, v); }
        v *= (1.f/16.f);
        float sc = gc1[t] * rsqrtf(v + BN_EPS);
        float sh = hc1[t] - m * sc;
#pragma unroll
        for (int b = 0; b < 16; b++) z1[b*256 + t] = fmaxf(0.f, fmaf(acc[b], sc, sh));
    }
    __syncthreads();
    float* z2 = sb;
    if (t < 128) {
        float acc[16];
#pragma unroll
        for (int b = 0; b < 16; b++) acc[b] = bc2[t];
        for (int i = 0; i < 256; i++) {
            float w = Wc2[(size_t)i*128 + t];
#pragma unroll
            for (int b = 0; b < 16; b++) acc[b] = fmaf(z1[b*256 + i], w, acc[b]);
        }
        float m = 0.f;
#pragma unroll
        for (int b = 0; b < 16; b++) m += acc[b];
        m *= (1.f/16.f);
        float v = 0.f;
#pragma unroll
        for (int b = 0; b < 16; b++) { float d = acc[b]-m; v = fmaf(d, d, v); }
        v *= (1.f/16.f);
        float sc = gc2[t] * rsqrtf(v + BN_EPS);
        float sh = hc2[t] - m * sc;
#pragma unroll
        for (int b = 0; b < 16; b++) z2[b*128 + t] = fmaxf(0.f, fmaf(acc[b], sc, sh));
    }
    __syncthreads();
    if (t < 40) {
        float acc[16];
#pragma unroll
        for (int b = 0; b < 16; b++) acc[b] = bc3[t];
        for (int i = 0; i < 128; i++) {
            float w = Wc3[(size_t)i*40 + t];
#pragma unroll
            for (int b = 0; b < 16; b++) acc[b] = fmaf(z2[b*128 + i], w, acc[b]);
        }
#pragma unroll
        for (int b = 0; b < 16; b++) out[b*40 + t] = acc[b];
    }
}

// ---------------- driver ----------------
extern "C" void kernel_launch(void* const* d_in, const int* in_sizes, int n_in,
                              void* d_out, int out_size) {
    (void)in_sizes; (void)n_in; (void)out_size;
    const float* x   = (const float*)d_in[0];
    const float* W1  = (const float*)d_in[1];
    const float* g1  = (const float*)d_in[2];
    const float* b1  = (const float*)d_in[3];
    const float* W2  = (const float*)d_in[4];
    const float* g2  = (const float*)d_in[5];
    const float* b2  = (const float*)d_in[6];
    const float* W3  = (const float*)d_in[7];
    const float* g3  = (const float*)d_in[8];
    const float* b3  = (const float*)d_in[9];
    const float* W4  = (const float*)d_in[10];
    const float* g4  = (const float*)d_in[11];
    const float* b4  = (const float*)d_in[12];
    const float* W5  = (const float*)d_in[13];
    const float* g5  = (const float*)d_in[14];
    const float* b5  = (const float*)d_in[15];
    const float* Wc1 = (const float*)d_in[16];
    const float* bc1 = (const float*)d_in[17];
    const float* gc1 = (const float*)d_in[18];
    const float* hc1 = (const float*)d_in[19];
    const float* Wc2 = (const float*)d_in[20];
    const float* bc2 = (const float*)d_in[21];
    const float* gc2 = (const float*)d_in[22];
    const float* hc2 = (const float*)d_in[23];
    const float* Wc3 = (const float*)d_in[24];
    const float* bc3 = (const float*)d_in[25];
    float* out = (float*)d_out;

    float *ybuf, *h0, *p1, *h1, *p2, *h2, *p3, *h3, *p4, *h4, *part0, *scale, *shift;
    int* knn;
    cudaGetSymbolAddress((void**)&ybuf,  g_ybuf);
    cudaGetSymbolAddress((void**)&h0,    g_h0);
    cudaGetSymbolAddress((void**)&p1,    g_p1);
    cudaGetSymbolAddress((void**)&h1,    g_h1);
    cudaGetSymbolAddress((void**)&p2,    g_p2);
    cudaGetSymbolAddress((void**)&h2,    g_h2);
    cudaGetSymbolAddress((void**)&p3,    g_p3);
    cudaGetSymbolAddress((void**)&h3,    g_h3);
    cudaGetSymbolAddress((void**)&p4,    g_p4);
    cudaGetSymbolAddress((void**)&h4,    g_h4);
    cudaGetSymbolAddress((void**)&knn,   g_knn);
    cudaGetSymbolAddress((void**)&part0, g_part);
    cudaGetSymbolAddress((void**)&scale, g_scale);
    cudaGetSymbolAddress((void**)&shift, g_shift);

    // carve scratch from ybuf (temporally disjoint with stage0's use of ybuf[0..2M))
    float* ymax  = ybuf;                       // <= 1,048,576 floats
    float* ymin  = ybuf + 1048576;
    float* part  = ybuf + 2097152;             // <= 2,097,152 floats (TD1)
    float* part2 = ybuf + 4194304;             // <= 65,536 floats
    const int NR = 64;

    // ---- stage 0: h0 = relu(bn(x @ W1)) ----
    s0_gemm<<<(16*4096*32 + 255)/256, 256>>>(x, W1, ybuf);
    stats_partial<<<512, 256>>>(ybuf, 16*4096, 32, part0);
    stats_final<<<1, 32>>>(part0, 512, 32, (float)(16*4096), g1, b1, scale, shift);
    normalize_kernel<<<(16*4096*32 + 255)/256, 256>>>(ybuf, scale, shift, 16*4096*32, 32, h0);

    // ---- TD1: 4096 -> 1024, C=32 -> D=64 ----
    fps_kernel<4096, 512><<<16, 512>>>(x, 1024, p1);
    knn_kernel<<<16*1024, 128, 4096*4>>>(x, p1, 4096, 1024, knn);
    td_gemm_fused<<<16*1024, 64, 16*35*4>>>(x, h0, p1, knn, W2, 4096, 1024, 32, 64, ymax, ymin, part);
    stats_reduce<<<NR, 64>>>(part, 16*1024, 64, part2);
    stats_final<<<1, 64>>>(part2, NR, 64, (float)(16*1024*16), g2, b2, scale, shift);
    td_norm<<<(16*1024*64 + 255)/256, 256>>>(ymax, ymin, scale, shift, 16*1024*64, 64, h1);

    // ---- TD2: 1024 -> 256, C=64 -> D=128 ----
    fps_kernel<1024, 256><<<16, 256>>>(p1, 256, p2);
    knn_kernel<<<16*256, 128, 1024*4>>>(p1, p2, 1024, 256, knn);
    td_gemm_fused<<<16*256, 128, 16*67*4>>>(p1, h1, p2, knn, W3, 1024, 256, 64, 128, ymax, ymin, part);
    stats_reduce<<<NR, 128>>>(part, 16*256, 128, part2);
    stats_final<<<1, 128>>>(part2, NR, 128, (float)(16*256*16), g3, b3, scale, shift);
    td_norm<<<(16*256*128 + 255)/256, 256>>>(ymax, ymin, scale, shift, 16*256*128, 128, h2);

    // ---- TD3: 256 -> 64, C=128 -> D=256 ----
    fps_kernel<256, 256><<<16, 256>>>(p2, 64, p3);
    knn_kernel<<<16*64, 128, 256*4>>>(p2, p3, 256, 64, knn);
    td_gemm_fused<<<16*64, 256, 16*131*4>>>(p2, h2, p3, knn, W4, 256, 64, 128, 256, ymax, ymin, part);
    stats_reduce<<<NR, 256>>>(part, 16*64, 256, part2);
    stats_final<<<1, 256>>>(part2, NR, 256, (float)(16*64*16), g4, b4, scale, shift);
    td_norm<<<(16*64*256 + 255)/256, 256>>>(ymax, ymin, scale, shift, 16*64*256, 256, h3);

    // ---- TD4: 64 -> 16, C=256 -> D=512 ----
    fps_kernel<64, 64><<<16, 64>>>(p3, 16, p4);
    knn_kernel<<<16*16, 128, 64*4>>>(p3, p4, 64, 16, knn);
    td_gemm_fused<<<16*16, 512, 16*259*4>>>(p3, h3, p4, knn, W5, 64, 16, 256, 512, ymax, ymin, part);
    stats_reduce<<<NR, 512>>>(part, 16*16, 512, part2);
    stats_final<<<1, 512>>>(part2, NR, 512, (float)(16*16*16), g5, b5, scale, shift);
    td_norm<<<(16*16*512 + 255)/256, 256>>>(ymax, ymin, scale, shift, 16*16*512, 512, h4);

    // ---- classifier head ----
    classifier_kernel<<<1, 256>>>(h4, Wc1, bc1, gc1, hc1, Wc2, bc2, gc2, hc2, Wc3, bc3, out);
}

// round 7
// speedup vs baseline: 2.1241x; 1.8783x over previous
#include <cuda_runtime.h>
#include <math.h>

#define BN_EPS 1e-5f

// ---------------- scratch (static device globals; no allocations) ----------------
__device__ float g_ybuf[16*1024*16*64];   // carved: stage0 ybuf | ymax | ymin | part | part2
__device__ float g_h0[16*4096*32];
__device__ float g_p1[16*1024*3];
__device__ float g_h1[16*1024*64];
__device__ float g_p2[16*256*3];
__device__ float g_h2[16*256*128];
__device__ float g_p3[16*64*3];
__device__ float g_h3[16*64*256];
__device__ float g_p4[16*16*3];
__device__ float g_h4[16*16*512];
__device__ int   g_knn[16*1024*16];
__device__ float g_part[512*2*512];       // stage0 partials [NB][2][D]
__device__ float g_scale[512];
__device__ float g_shift[512];

// ---------------- FPS: one block per batch, points in registers, REDUX argmax ----------------
// (R4-proven variant: 3 barriers/step, thread0 combine, smem coord broadcast. Do not modify.)
template<int N, int T>
__global__ void fps_kernel(const float* __restrict__ p, int M, float* __restrict__ newp) {
    constexpr int NPT = N / T;
    constexpr int NW  = T / 32;
    const int b = blockIdx.x, tid = threadIdx.x;
    const float* pb = p + (size_t)b * N * 3;
    float lx[NPT], ly[NPT], lz[NPT], md[NPT];
#pragma unroll
    for (int j = 0; j < NPT; j++) {
        int g = j * T + tid;
        lx[j] = pb[g*3+0]; ly[j] = pb[g*3+1]; lz[j] = pb[g*3+2];
        md[j] = INFINITY;
    }
    __shared__ unsigned s_wd[16];
    __shared__ int      s_wi[16];
    __shared__ float    s_b[3];
    if (tid == 0) {
        s_b[0] = pb[0]; s_b[1] = pb[1]; s_b[2] = pb[2];
        float* o = newp + (size_t)b * M * 3;
        o[0] = pb[0]; o[1] = pb[1]; o[2] = pb[2];
    }
    __syncthreads();
    float bx = s_b[0], by = s_b[1], bz = s_b[2];
    for (int t = 1; t < M; t++) {
        // local update + argmax (first-index tie-break via sentinel init)
        float best = 0.0f; int besti = 0x7fffffff;
#pragma unroll
        for (int j = 0; j < NPT; j++) {
            float dx = lx[j]-bx, dy = ly[j]-by, dz = lz[j]-bz;
            float d = dx*dx + dy*dy + dz*dz;
            float v = fminf(md[j], d);
            md[j] = v;
            int g = j * T + tid;
            if (v > best || (v == best && g < besti)) { best = v; besti = g; }
        }
        // warp argmax via REDUX (dists >= 0 so float bits are order-preserving)
        unsigned bb = __float_as_uint(best);
        unsigned mb = __reduce_max_sync(0xffffffffu, bb);
        int cand = (bb == mb) ? besti : 0x7fffffff;
        int wbi = __reduce_min_sync(0xffffffffu, cand);
        if ((tid & 31) == 0) { s_wd[tid >> 5] = mb; s_wi[tid >> 5] = wbi; }
        __syncthreads();
        if (tid < 32) {
            unsigned u = (tid < NW) ? s_wd[tid] : 0u;
            int      ii = (tid < NW) ? s_wi[tid] : 0x7fffffff;
            unsigned m2 = __reduce_max_sync(0xffffffffu, u);
            int c2 = (u == m2) ? ii : 0x7fffffff;
            int win = __reduce_min_sync(0xffffffffu, c2);
            if (tid == 0) {
                const float* wp = pb + (size_t)win * 3;   // L1-hot (48KB, warmed at init)
                float cx = wp[0], cy = wp[1], cz = wp[2];
                s_b[0] = cx; s_b[1] = cy; s_b[2] = cz;
                float* o = newp + ((size_t)b * M + t) * 3;
                o[0] = cx; o[1] = cy; o[2] = cz;
            }
        }
        __syncthreads();
        bx = s_b[0]; by = s_b[1]; bz = s_b[2];
    }
}

// ---------------- kNN: 256 threads, cached per-thread minima, one owner rescan per round ----------------
__global__ void knn_kernel(const float* __restrict__ p, const float* __restrict__ newp,
                           int N, int M, int* __restrict__ knn) {
    extern __shared__ float dist[];          // N floats
    __shared__ float s_tmin[256];
    __shared__ int   s_tidx[256];
    __shared__ int   s_win;
    const int q = blockIdx.x;
    const int b = q / M;
    const int tid = threadIdx.x;
    const float* pb = p + (size_t)b * N * 3;
    const float qx = newp[q*3+0], qy = newp[q*3+1], qz = newp[q*3+2];
    float bd = INFINITY; int bi = 0x7fffffff;
    for (int n = tid; n < N; n += 256) {
        float dx = qx - pb[n*3+0], dy = qy - pb[n*3+1], dz = qz - pb[n*3+2];
        float d = dx*dx + dy*dy + dz*dz;
        dist[n] = d;
        if (d < bd) { bd = d; bi = n; }      // ascending n -> first-index ties
    }
    s_tmin[tid] = bd; s_tidx[tid] = bi;
    __syncthreads();
    for (int r = 0; ; r++) {
        if (tid < 32) {
            float m0 = s_tmin[tid]; int i0 = s_tidx[tid];
#pragma unroll
            for (int off = 32; off < 256; off += 32) {
                float mm = s_tmin[tid + off]; int ii = s_tidx[tid + off];
                if (mm < m0 || (mm == m0 && ii < i0)) { m0 = mm; i0 = ii; }
            }
            unsigned b0 = __float_as_uint(m0);
            unsigned mb = __reduce_min_sync(0xffffffffu, b0);
            int cand = (b0 == mb) ? i0 : 0x7fffffff;
            int win = __reduce_min_sync(0xffffffffu, cand);
            if (tid == 0) { knn[(size_t)q*16 + r] = win; s_win = win; }
        }
        __syncthreads();
        if (r == 15) break;
        int win = s_win;
        if ((win & 255) == tid) {            // owner rescans its slice
            dist[win] = INFINITY;
            float nb = INFINITY; int ni = 0x7fffffff;
            for (int n = tid; n < N; n += 256) {
                float d = dist[n];
                if (d < nb) { nb = d; ni = n; }
            }
            s_tmin[tid] = nb; s_tidx[tid] = ni;
        }
        __syncthreads();
    }
}

// ---------------- fused grouped GEMM + max/min over k + per-block channel stats ----------------
__global__ void td_gemm_fused(const float* __restrict__ p, const float* __restrict__ h,
                              const float* __restrict__ newp, const int* __restrict__ knn,
                              const float* __restrict__ W, int N, int M, int C, int D,
                              float* __restrict__ ymax, float* __restrict__ ymin,
                              float* __restrict__ part) {
    extern __shared__ float feat[];          // 16*(C+3)
    __shared__ int   s_knn[16];
    __shared__ float s_np[3];
    const int q = blockIdx.x;
    const int b = q / M;
    const int t = threadIdx.x;               // D threads, one per output channel
    if (t < 16) s_knn[t] = knn[(size_t)q*16 + t];
    if (t < 3)  s_np[t]  = newp[q*3 + t];
    __syncthreads();
    const int F = C + 3;
    const float* pb = p + (size_t)b * N * 3;
    const float* hb = h + (size_t)b * N * C;
    for (int e = t; e < 16 * F; e += D) {
        int k = e / F, c = e - k * F;
        int n = s_knn[k];
        feat[e] = (c < 3) ? (pb[n*3 + c] - s_np[c]) : hb[(size_t)n * C + (c - 3)];
    }
    __syncthreads();
    float acc[16];
#pragma unroll
    for (int k = 0; k < 16; k++) acc[k] = 0.f;
#pragma unroll 2
    for (int c = 0; c < F; c++) {
        float w = W[(size_t)c * D + t];      // loaded once per c
#pragma unroll
        for (int k = 0; k < 16; k++) acc[k] += feat[k*F + c] * w;   // LDS broadcast
    }
    float mx = -INFINITY, mn = INFINITY, s = 0.f, s2 = 0.f;
#pragma unroll
    for (int k = 0; k < 16; k++) {
        float v = acc[k];
        mx = fmaxf(mx, v); mn = fminf(mn, v);
        s += v; s2 += v * v;
    }
    ymax[(size_t)q * D + t] = mx;
    ymin[(size_t)q * D + t] = mn;
    part[(size_t)q * 2 * D + t]     = s;
    part[(size_t)q * 2 * D + D + t] = s2;
}

// ---------------- stats tree: level-1 reduce of per-block partials ----------------
__global__ void stats_reduce(const float* __restrict__ part, int Q, int D,
                             float* __restrict__ out) {
    const int t = threadIdx.x;               // D threads
    const int per = (Q + gridDim.x - 1) / gridDim.x;
    const int r0 = blockIdx.x * per;
    const int r1 = min(r0 + per, Q);
    float s = 0.f, s2 = 0.f;
    for (int r = r0; r < r1; r++) {
        s  += part[(size_t)r * 2 * D + t];
        s2 += part[(size_t)r * 2 * D + D + t];
    }
    out[(size_t)blockIdx.x * 2 * D + t]     = s;
    out[(size_t)blockIdx.x * 2 * D + D + t] = s2;
}

__global__ void stats_final(const float* __restrict__ part, int NB, int D, float cnt,
                            const float* __restrict__ g, const float* __restrict__ bta,
                            float* __restrict__ scale, float* __restrict__ shift) {
    const int c = threadIdx.x;
    if (c >= D) return;
    float S = 0.f, Q2 = 0.f;
    for (int i = 0; i < NB; i++) {
        S  += part[(size_t)i * 2 * D + c];
        Q2 += part[(size_t)i * 2 * D + D + c];
    }
    float m = S / cnt;
    float v = Q2 / cnt - m * m;
    float sc = g[c] * rsqrtf(v + BN_EPS);
    scale[c] = sc;
    shift[c] = bta[c] - m * sc;
}

// ---------------- apply BN+ReLU to the sign-appropriate extremum ----------------
__global__ void td_norm(const float* __restrict__ ymax, const float* __restrict__ ymin,
                        const float* __restrict__ scale, const float* __restrict__ shift,
                        int total, int D, float* __restrict__ hout) {
    int i = blockIdx.x * 256 + threadIdx.x;
    if (i >= total) return;
    int d = i % D;
    float sc = scale[d];
    float v = (sc >= 0.f) ? ymax[i] : ymin[i];
    hout[i] = fmaxf(0.f, sc * v + shift[d]);
}

// ---------------- stage 0: h = p @ W1 (3->32) ----------------
__global__ void s0_gemm(const float* __restrict__ x, const float* __restrict__ W1,
                        float* __restrict__ y) {
    int i = blockIdx.x * 256 + threadIdx.x;
    if (i >= 16*4096*32) return;
    int pt = i >> 5, c = i & 31;
    const float* xp = x + (size_t)pt * 3;
    y[i] = xp[0]*W1[c] + xp[1]*W1[32+c] + xp[2]*W1[64+c];
}

__global__ void stats_partial(const float* __restrict__ y, int Q, int D, float* __restrict__ part) {
    const int NB = gridDim.x;
    const int rpb = (Q + NB - 1) / NB;
    const int r0 = blockIdx.x * rpb;
    const int r1 = min(r0 + rpb, Q);
    __shared__ float ss[256], sq[256];
    const int tid = threadIdx.x;
    const int rpi = 256 / D;
    const int c = tid % D;
    const int ro = tid / D;
    float s = 0.f, q2 = 0.f;
    for (int r = r0 + ro; r < r1; r += rpi) {
        float v = y[(size_t)r * D + c]; s += v; q2 += v * v;
    }
    ss[tid] = s; sq[tid] = q2;
    __syncthreads();
    if (tid < D) {
        for (int o = 1; o < rpi; o++) { s += ss[tid + o*D]; q2 += sq[tid + o*D]; }
        part[(size_t)blockIdx.x * 2 * D + tid]     = s;
        part[(size_t)blockIdx.x * 2 * D + D + tid] = q2;
    }
}

__global__ void normalize_kernel(const float* __restrict__ y, const float* __restrict__ scale,
                                 const float* __restrict__ shift, int total, int D,
                                 float* __restrict__ out) {
    int i = blockIdx.x * 256 + threadIdx.x;
    if (i >= total) return;
    int c = i % D;
    out[i] = fmaxf(0.f, y[i] * scale[c] + shift[c]);
}

// ---------------- classifier head: single block, channel-per-thread ----------------
__global__ void classifier_kernel(const float* __restrict__ h4,
                                  const float* __restrict__ Wc1, const float* __restrict__ bc1,
                                  const float* __restrict__ gc1, const float* __restrict__ hc1,
                                  const float* __restrict__ Wc2, const float* __restrict__ bc2,
                                  const float* __restrict__ gc2, const float* __restrict__ hc2,
                                  const float* __restrict__ Wc3, const float* __restrict__ bc3,
                                  float* __restrict__ out) {
    __shared__ float sb[12288];
    float* z  = sb;
    float* z1 = sb + 8192;
    const int t = threadIdx.x;  // 256 threads
    for (int e = t; e < 8192; e += 256) {
        int b = e >> 9, c = e & 511;
        float s = 0.f;
        for (int k = 0; k < 16; k++) s += h4[((size_t)(b*16 + k))*512 + c];
        z[e] = s * (1.f/16.f);
    }
    __syncthreads();
    {
        float acc[16];
#pragma unroll
        for (int b = 0; b < 16; b++) acc[b] = bc1[t];
        for (int i = 0; i < 512; i++) {
            float w = Wc1[(size_t)i*256 + t];
#pragma unroll
            for (int b = 0; b < 16; b++) acc[b] += z[b*512 + i] * w;
        }
        float m = 0.f;
#pragma unroll
        for (int b = 0; b < 16; b++) m += acc[b];
        m *= (1.f/16.f);
        float v = 0.f;
#pragma unroll
        for (int b = 0; b < 16; b++) { float d = acc[b]-m; v += d*d; }
        v *= (1.f/16.f);
        float sc = gc1[t] * rsqrtf(v + BN_EPS);
        float sh = hc1[t] - m * sc;
#pragma unroll
        for (int b = 0; b < 16; b++) z1[b*256 + t] = fmaxf(0.f, acc[b]*sc + sh);
    }
    __syncthreads();
    float* z2 = sb;
    if (t < 128) {
        float acc[16];
#pragma unroll
        for (int b = 0; b < 16; b++) acc[b] = bc2[t];
        for (int i = 0; i < 256; i++) {
            float w = Wc2[(size_t)i*128 + t];
#pragma unroll
            for (int b = 0; b < 16; b++) acc[b] += z1[b*256 + i] * w;
        }
        float m = 0.f;
#pragma unroll
        for (int b = 0; b < 16; b++) m += acc[b];
        m *= (1.f/16.f);
        float v = 0.f;
#pragma unroll
        for (int b = 0; b < 16; b++) { float d = acc[b]-m; v += d*d; }
        v *= (1.f/16.f);
        float sc = gc2[t] * rsqrtf(v + BN_EPS);
        float sh = hc2[t] - m * sc;
#pragma unroll
        for (int b = 0; b < 16; b++) z2[b*128 + t] = fmaxf(0.f, acc[b]*sc + sh);
    }
    __syncthreads();
    if (t < 40) {
        float acc[16];
#pragma unroll
        for (int b = 0; b < 16; b++) acc[b] = bc3[t];
        for (int i = 0; i < 128; i++) {
            float w = Wc3[(size_t)i*40 + t];
#pragma unroll
            for (int b = 0; b < 16; b++) acc[b] += z2[b*128 + i] * w;
        }
#pragma unroll
        for (int b = 0; b < 16; b++) out[b*40 + t] = acc[b];
    }
}

// ---------------- driver ----------------
extern "C" void kernel_launch(void* const* d_in, const int* in_sizes, int n_in,
                              void* d_out, int out_size) {
    (void)in_sizes; (void)n_in; (void)out_size;
    const float* x   = (const float*)d_in[0];
    const float* W1  = (const float*)d_in[1];
    const float* g1  = (const float*)d_in[2];
    const float* b1  = (const float*)d_in[3];
    const float* W2  = (const float*)d_in[4];
    const float* g2  = (const float*)d_in[5];
    const float* b2  = (const float*)d_in[6];
    const float* W3  = (const float*)d_in[7];
    const float* g3  = (const float*)d_in[8];
    const float* b3  = (const float*)d_in[9];
    const float* W4  = (const float*)d_in[10];
    const float* g4  = (const float*)d_in[11];
    const float* b4  = (const float*)d_in[12];
    const float* W5  = (const float*)d_in[13];
    const float* g5  = (const float*)d_in[14];
    const float* b5  = (const float*)d_in[15];
    const float* Wc1 = (const float*)d_in[16];
    const float* bc1 = (const float*)d_in[17];
    const float* gc1 = (const float*)d_in[18];
    const float* hc1 = (const float*)d_in[19];
    const float* Wc2 = (const float*)d_in[20];
    const float* bc2 = (const float*)d_in[21];
    const float* gc2 = (const float*)d_in[22];
    const float* hc2 = (const float*)d_in[23];
    const float* Wc3 = (const float*)d_in[24];
    const float* bc3 = (const float*)d_in[25];
    float* out = (float*)d_out;

    float *ybuf, *h0, *p1, *h1, *p2, *h2, *p3, *h3, *p4, *h4, *part0, *scale, *shift;
    int* knn;
    cudaGetSymbolAddress((void**)&ybuf,  g_ybuf);
    cudaGetSymbolAddress((void**)&h0,    g_h0);
    cudaGetSymbolAddress((void**)&p1,    g_p1);
    cudaGetSymbolAddress((void**)&h1,    g_h1);
    cudaGetSymbolAddress((void**)&p2,    g_p2);
    cudaGetSymbolAddress((void**)&h2,    g_h2);
    cudaGetSymbolAddress((void**)&p3,    g_p3);
    cudaGetSymbolAddress((void**)&h3,    g_h3);
    cudaGetSymbolAddress((void**)&p4,    g_p4);
    cudaGetSymbolAddress((void**)&h4,    g_h4);
    cudaGetSymbolAddress((void**)&knn,   g_knn);
    cudaGetSymbolAddress((void**)&part0, g_part);
    cudaGetSymbolAddress((void**)&scale, g_scale);
    cudaGetSymbolAddress((void**)&shift, g_shift);

    // carve scratch from ybuf (temporally disjoint with stage0's use of ybuf[0..2M))
    float* ymax  = ybuf;                       // <= 1,048,576 floats
    float* ymin  = ybuf + 1048576;
    float* part  = ybuf + 2097152;             // <= 2,097,152 floats (TD1)
    float* part2 = ybuf + 4194304;             // <= 65,536 floats
    const int NR = 64;

    // ---- stage 0: h0 = relu(bn(x @ W1)) ----
    s0_gemm<<<(16*4096*32 + 255)/256, 256>>>(x, W1, ybuf);
    stats_partial<<<512, 256>>>(ybuf, 16*4096, 32, part0);
    stats_final<<<1, 32>>>(part0, 512, 32, (float)(16*4096), g1, b1, scale, shift);
    normalize_kernel<<<(16*4096*32 + 255)/256, 256>>>(ybuf, scale, shift, 16*4096*32, 32, h0);

    // ---- TD1: 4096 -> 1024, C=32 -> D=64 ----
    fps_kernel<4096, 512><<<16, 512>>>(x, 1024, p1);
    knn_kernel<<<16*1024, 256, 4096*4>>>(x, p1, 4096, 1024, knn);
    td_gemm_fused<<<16*1024, 64, 16*35*4>>>(x, h0, p1, knn, W2, 4096, 1024, 32, 64, ymax, ymin, part);
    stats_reduce<<<NR, 64>>>(part, 16*1024, 64, part2);
    stats_final<<<1, 64>>>(part2, NR, 64, (float)(16*1024*16), g2, b2, scale, shift);
    td_norm<<<(16*1024*64 + 255)/256, 256>>>(ymax, ymin, scale, shift, 16*1024*64, 64, h1);

    // ---- TD2: 1024 -> 256, C=64 -> D=128 ----
    fps_kernel<1024, 256><<<16, 256>>>(p1, 256, p2);
    knn_kernel<<<16*256, 256, 1024*4>>>(p1, p2, 1024, 256, knn);
    td_gemm_fused<<<16*256, 128, 16*67*4>>>(p1, h1, p2, knn, W3, 1024, 256, 64, 128, ymax, ymin, part);
    stats_reduce<<<NR, 128>>>(part, 16*256, 128, part2);
    stats_final<<<1, 128>>>(part2, NR, 128, (float)(16*256*16), g3, b3, scale, shift);
    td_norm<<<(16*256*128 + 255)/256, 256>>>(ymax, ymin, scale, shift, 16*256*128, 128, h2);

    // ---- TD3: 256 -> 64, C=128 -> D=256 ----
    fps_kernel<256, 256><<<16, 256>>>(p2, 64, p3);
    knn_kernel<<<16*64, 256, 256*4>>>(p2, p3, 256, 64, knn);
    td_gemm_fused<<<16*64, 256, 16*131*4>>>(p2, h2, p3, knn, W4, 256, 64, 128, 256, ymax, ymin, part);
    stats_reduce<<<NR, 256>>>(part, 16*64, 256, part2);
    stats_final<<<1, 256>>>(part2, NR, 256, (float)(16*64*16), g4, b4, scale, shift);
    td_norm<<<(16*64*256 + 255)/256, 256>>>(ymax, ymin, scale, shift, 16*64*256, 256, h3);

    // ---- TD4: 64 -> 16, C=256 -> D=512 ----
    fps_kernel<64, 64><<<16, 64>>>(p3, 16, p4);
    knn_kernel<<<16*16, 256, 64*4>>>(p3, p4, 64, 16, knn);
    td_gemm_fused<<<16*16, 512, 16*259*4>>>(p3, h3, p4, knn, W5, 64, 16, 256, 512, ymax, ymin, part);
    stats_reduce<<<NR, 512>>>(part, 16*16, 512, part2);
    stats_final<<<1, 512>>>(part2, NR, 512, (float)(16*16*16), g5, b5, scale, shift);
    td_norm<<<(16*16*512 + 255)/256, 256>>>(ymax, ymin, scale, shift, 16*16*512, 512, h4);

    // ---- classifier head ----
    classifier_kernel<<<1, 256>>>(h4, Wc1, bc1, gc1, hc1, Wc2, bc2, gc2, hc2, Wc3, bc3, out);
}

// round 9
// speedup vs baseline: 2.3353x; 1.0994x over previous
#include <cuda_runtime.h>
#include <math.h>

#define BN_EPS 1e-5f

// packed f32x2 helpers (sm_100+; FFMA2/FADD2 SASS only reachable via PTX)
#define F32X2_PACK(o, lo, hi)  asm("mov.b64 %0, {%1, %2};" : "=l"(o) : "f"(lo), "f"(hi))
#define F32X2_UNPACK(lo, hi, i) asm("mov.b64 {%0, %1}, %2;" : "=f"(lo), "=f"(hi) : "l"(i))
#define F32X2_ADD(o, a, b)     asm("add.rn.f32x2 %0, %1, %2;" : "=l"(o) : "l"(a), "l"(b))
#define F32X2_MUL(o, a, b)     asm("mul.rn.f32x2 %0, %1, %2;" : "=l"(o) : "l"(a), "l"(b))
#define F32X2_FMA(o, a, b, c)  asm("fma.rn.f32x2 %0, %1, %2, %3;" : "=l"(o) : "l"(a), "l"(b), "l"(c))

// ---------------- scratch (static device globals; no allocations) ----------------
__device__ float g_ybuf[16*1024*16*64];   // carved: stage0 ybuf | ymax | ymin | part | part2
__device__ float g_h0[16*4096*32];
__device__ float g_p1[16*1024*3];
__device__ float g_h1[16*1024*64];
__device__ float g_p2[16*256*3];
__device__ float g_h2[16*256*128];
__device__ float g_p3[16*64*3];
__device__ float g_h3[16*64*256];
__device__ float g_p4[16*16*3];
__device__ float g_h4[16*16*512];
__device__ int   g_knn[16*1024*16];
__device__ float g_part[512*2*512];       // stage0 partials [NB][2][D]
__device__ float g_scale[512];
__device__ float g_shift[512];

// ---------------- FPS: one block per batch, R4-proven skeleton, packed f32x2 inner loop ----------------
template<int N, int T>
__global__ void fps_kernel(const float* __restrict__ p, int M, float* __restrict__ newp) {
    constexpr int NPT = N / T;
    constexpr int NW  = T / 32;
    const int b = blockIdx.x, tid = threadIdx.x;
    const float* pb = p + (size_t)b * N * 3;
    __shared__ unsigned s_wd[16];
    __shared__ int      s_wi[16];
    __shared__ float    s_b[3];
    if (tid == 0) {
        s_b[0] = pb[0]; s_b[1] = pb[1]; s_b[2] = pb[2];
        float* o = newp + (size_t)b * M * 3;
        o[0] = pb[0]; o[1] = pb[1]; o[2] = pb[2];
    }
    __syncthreads();
    float bx = s_b[0], by = s_b[1], bz = s_b[2];

    if constexpr (NPT >= 2) {
        constexpr int NP2 = NPT / 2;
        unsigned long long px2[NP2], py2[NP2], pz2[NP2];
        float md[NPT];
#pragma unroll
        for (int a = 0; a < NP2; a++) {
            int g0 = (2*a)   * T + tid;
            int g1 = (2*a+1) * T + tid;
            F32X2_PACK(px2[a], pb[g0*3+0], pb[g1*3+0]);
            F32X2_PACK(py2[a], pb[g0*3+1], pb[g1*3+1]);
            F32X2_PACK(pz2[a], pb[g0*3+2], pb[g1*3+2]);
            md[2*a] = INFINITY; md[2*a+1] = INFINITY;
        }
        for (int t = 1; t < M; t++) {
            float nbx = -bx, nby = -by, nbz = -bz;
            unsigned long long nbx2, nby2, nbz2;
            F32X2_PACK(nbx2, nbx, nbx);
            F32X2_PACK(nby2, nby, nby);
            F32X2_PACK(nbz2, nbz, nbz);
            float best = 0.0f; int besti = 0x7fffffff;
#pragma unroll
            for (int a = 0; a < NP2; a++) {
                unsigned long long dx2, dy2, dz2, t2;
                F32X2_ADD(dx2, px2[a], nbx2);           // lx - bx (IEEE-identical to sub)
                F32X2_ADD(dy2, py2[a], nby2);
                F32X2_ADD(dz2, pz2[a], nbz2);
                F32X2_MUL(t2, dz2, dz2);                // dz*dz
                F32X2_FMA(t2, dy2, dy2, t2);            // dy*dy + .
                F32X2_FMA(t2, dx2, dx2, t2);            // dx*dx + .  (== fmaf chain in R4)
                float d0, d1;
                F32X2_UNPACK(d0, d1, t2);
                float v0 = fminf(md[2*a], d0);   md[2*a]   = v0;
                float v1 = fminf(md[2*a+1], d1); md[2*a+1] = v1;
                int g0 = (2*a)   * T + tid;
                int g1 = (2*a+1) * T + tid;
                if (v0 > best || (v0 == best && g0 < besti)) { best = v0; besti = g0; }
                if (v1 > best || (v1 == best && g1 < besti)) { best = v1; besti = g1; }
            }
            // warp argmax via REDUX (dists >= 0 so float bits are order-preserving)
            unsigned bb = __float_as_uint(best);
            unsigned mb = __reduce_max_sync(0xffffffffu, bb);
            int cand = (bb == mb) ? besti : 0x7fffffff;
            int wbi = __reduce_min_sync(0xffffffffu, cand);
            if ((tid & 31) == 0) { s_wd[tid >> 5] = mb; s_wi[tid >> 5] = wbi; }
            __syncthreads();
            if (tid < 32) {
                unsigned u = (tid < NW) ? s_wd[tid] : 0u;
                int      ii = (tid < NW) ? s_wi[tid] : 0x7fffffff;
                unsigned m2 = __reduce_max_sync(0xffffffffu, u);
                int c2 = (u == m2) ? ii : 0x7fffffff;
                int win = __reduce_min_sync(0xffffffffu, c2);
                if (tid == 0) {
                    const float* wp = pb + (size_t)win * 3;   // L1-hot
                    float cx = wp[0], cy = wp[1], cz = wp[2];
                    s_b[0] = cx; s_b[1] = cy; s_b[2] = cz;
                    float* o = newp + ((size_t)b * M + t) * 3;
                    o[0] = cx; o[1] = cy; o[2] = cz;
                }
            }
            __syncthreads();
            bx = s_b[0]; by = s_b[1]; bz = s_b[2];
        }
    } else {
        // scalar path (NPT == 1): identical to R4
        float lx = pb[tid*3+0], ly = pb[tid*3+1], lz = pb[tid*3+2], md = INFINITY;
        for (int t = 1; t < M; t++) {
            float best = 0.0f; int besti = 0x7fffffff;
            float dx = lx-bx, dy = ly-by, dz = lz-bz;
            float d = fmaf(dx, dx, fmaf(dy, dy, dz*dz));
            float v = fminf(md, d);
            md = v;
            if (v > best || (v == best && tid < besti)) { best = v; besti = tid; }
            unsigned bb = __float_as_uint(best);
            unsigned mb = __reduce_max_sync(0xffffffffu, bb);
            int cand = (bb == mb) ? besti : 0x7fffffff;
            int wbi = __reduce_min_sync(0xffffffffu, cand);
            if ((tid & 31) == 0) { s_wd[tid >> 5] = mb; s_wi[tid >> 5] = wbi; }
            __syncthreads();
            if (tid < 32) {
                unsigned u = (tid < NW) ? s_wd[tid] : 0u;
                int      ii = (tid < NW) ? s_wi[tid] : 0x7fffffff;
                unsigned m2 = __reduce_max_sync(0xffffffffu, u);
                int c2 = (u == m2) ? ii : 0x7fffffff;
                int win = __reduce_min_sync(0xffffffffu, c2);
                if (tid == 0) {
                    const float* wp = pb + (size_t)win * 3;
                    float cx = wp[0], cy = wp[1], cz = wp[2];
                    s_b[0] = cx; s_b[1] = cy; s_b[2] = cz;
                    float* o = newp + ((size_t)b * M + t) * 3;
                    o[0] = cx; o[1] = cy; o[2] = cz;
                }
            }
            __syncthreads();
            bx = s_b[0]; by = s_b[1]; bz = s_b[2];
        }
    }
}

// ---------------- kNN (exact R4 variant): 128 thr, cached per-thread minima, owner rescan ----------------
__global__ void knn_kernel(const float* __restrict__ p, const float* __restrict__ newp,
                           int N, int M, int* __restrict__ knn) {
    extern __shared__ float dist[];          // N floats
    __shared__ float s_tmin[128];
    __shared__ int   s_tidx[128];
    __shared__ int   s_win;
    const int q = blockIdx.x;
    const int b = q / M;
    const int tid = threadIdx.x;
    const float* pb = p + (size_t)b * N * 3;
    const float qx = newp[q*3+0], qy = newp[q*3+1], qz = newp[q*3+2];
    float bd = INFINITY; int bi = 0x7fffffff;
    for (int n = tid; n < N; n += 128) {
        float dx = qx - pb[n*3+0], dy = qy - pb[n*3+1], dz = qz - pb[n*3+2];
        float d = fmaf(dx, dx, fmaf(dy, dy, dz*dz));
        dist[n] = d;
        if (d < bd) { bd = d; bi = n; }      // ascending n -> first-index ties
    }
    s_tmin[tid] = bd; s_tidx[tid] = bi;
    __syncthreads();
    for (int r = 0; ; r++) {
        if (tid < 32) {
            float m0 = s_tmin[tid]; int i0 = s_tidx[tid];
#pragma unroll
            for (int off = 32; off < 128; off += 32) {
                float mm = s_tmin[tid + off]; int ii = s_tidx[tid + off];
                if (mm < m0 || (mm == m0 && ii < i0)) { m0 = mm; i0 = ii; }
            }
            unsigned b0 = __float_as_uint(m0);
            unsigned mb = __reduce_min_sync(0xffffffffu, b0);
            int cand = (b0 == mb) ? i0 : 0x7fffffff;
            int win = __reduce_min_sync(0xffffffffu, cand);
            if (tid == 0) { knn[(size_t)q*16 + r] = win; s_win = win; }
        }
        __syncthreads();
        if (r == 15) break;
        int win = s_win;
        if ((win & 127) == tid) {            // owner rescans its slice
            dist[win] = INFINITY;
            float nb = INFINITY; int ni = 0x7fffffff;
            for (int n = tid; n < N; n += 128) {
                float d = dist[n];
                if (d < nb) { nb = d; ni = n; }
            }
            s_tmin[tid] = nb; s_tidx[tid] = ni;
        }
        __syncthreads();
    }
}

// ---------------- fused grouped GEMM + max/min over k + per-block channel stats ----------------
__global__ void td_gemm_fused(const float* __restrict__ p, const float* __restrict__ h,
                              const float* __restrict__ newp, const int* __restrict__ knn,
                              const float* __restrict__ W, int N, int M, int C, int D,
                              float* __restrict__ ymax, float* __restrict__ ymin,
                              float* __restrict__ part) {
    extern __shared__ float feat[];          // 16*(C+3)
    __shared__ int   s_knn[16];
    __shared__ float s_np[3];
    const int q = blockIdx.x;
    const int b = q / M;
    const int t = threadIdx.x;               // D threads, one per output channel
    if (t < 16) s_knn[t] = knn[(size_t)q*16 + t];
    if (t < 3)  s_np[t]  = newp[q*3 + t];
    __syncthreads();
    const int F = C + 3;
    const float* pb = p + (size_t)b * N * 3;
    const float* hb = h + (size_t)b * N * C;
    for (int e = t; e < 16 * F; e += D) {
        int k = e / F, c = e - k * F;
        int n = s_knn[k];
        feat[e] = (c < 3) ? (pb[n*3 + c] - s_np[c]) : hb[(size_t)n * C + (c - 3)];
    }
    __syncthreads();
    float acc[16];
#pragma unroll
    for (int k = 0; k < 16; k++) acc[k] = 0.f;
#pragma unroll 2
    for (int c = 0; c < F; c++) {
        float w = W[(size_t)c * D + t];      // loaded once per c
#pragma unroll
        for (int k = 0; k < 16; k++) acc[k] += feat[k*F + c] * w;   // LDS broadcast
    }
    float mx = -INFINITY, mn = INFINITY, s = 0.f, s2 = 0.f;
#pragma unroll
    for (int k = 0; k < 16; k++) {
        float v = acc[k];
        mx = fmaxf(mx, v); mn = fminf(mn, v);
        s += v; s2 += v * v;
    }
    ymax[(size_t)q * D + t] = mx;
    ymin[(size_t)q * D + t] = mn;
    part[(size_t)q * 2 * D + t]     = s;
    part[(size_t)q * 2 * D + D + t] = s2;
}

// ---------------- stats tree: level-1 reduce of per-block partials ----------------
__global__ void stats_reduce(const float* __restrict__ part, int Q, int D,
                             float* __restrict__ out) {
    const int t = threadIdx.x;               // D threads
    const int per = (Q + gridDim.x - 1) / gridDim.x;
    const int r0 = blockIdx.x * per;
    const int r1 = min(r0 + per, Q);
    float s = 0.f, s2 = 0.f;
    for (int r = r0; r < r1; r++) {
        s  += part[(size_t)r * 2 * D + t];
        s2 += part[(size_t)r * 2 * D + D + t];
    }
    out[(size_t)blockIdx.x * 2 * D + t]     = s;
    out[(size_t)blockIdx.x * 2 * D + D + t] = s2;
}

__global__ void stats_final(const float* __restrict__ part, int NB, int D, float cnt,
                            const float* __restrict__ g, const float* __restrict__ bta,
                            float* __restrict__ scale, float* __restrict__ shift) {
    const int c = threadIdx.x;
    if (c >= D) return;
    float S = 0.f, Q2 = 0.f;
    for (int i = 0; i < NB; i++) {
        S  += part[(size_t)i * 2 * D + c];
        Q2 += part[(size_t)i * 2 * D + D + c];
    }
    float m = S / cnt;
    float v = Q2 / cnt - m * m;
    float sc = g[c] * rsqrtf(v + BN_EPS);
    scale[c] = sc;
    shift[c] = bta[c] - m * sc;
}

// ---------------- apply BN+ReLU to the sign-appropriate extremum ----------------
__global__ void td_norm(const float* __restrict__ ymax, const float* __restrict__ ymin,
                        const float* __restrict__ scale, const float* __restrict__ shift,
                        int total, int D, float* __restrict__ hout) {
    int i = blockIdx.x * 256 + threadIdx.x;
    if (i >= total) return;
    int d = i % D;
    float sc = scale[d];
    float v = (sc >= 0.f) ? ymax[i] : ymin[i];
    hout[i] = fmaxf(0.f, sc * v + shift[d]);
}

// ---------------- stage 0: h = p @ W1 (3->32) ----------------
__global__ void s0_gemm(const float* __restrict__ x, const float* __restrict__ W1,
                        float* __restrict__ y) {
    int i = blockIdx.x * 256 + threadIdx.x;
    if (i >= 16*4096*32) return;
    int pt = i >> 5, c = i & 31;
    const float* xp = x + (size_t)pt * 3;
    y[i] = xp[0]*W1[c] + xp[1]*W1[32+c] + xp[2]*W1[64+c];
}

__global__ void stats_partial(const float* __restrict__ y, int Q, int D, float* __restrict__ part) {
    const int NB = gridDim.x;
    const int rpb = (Q + NB - 1) / NB;
    const int r0 = blockIdx.x * rpb;
    const int r1 = min(r0 + rpb, Q);
    __shared__ float ss[256], sq[256];
    const int tid = threadIdx.x;
    const int rpi = 256 / D;
    const int c = tid % D;
    const int ro = tid / D;
    float s = 0.f, q2 = 0.f;
    for (int r = r0 + ro; r < r1; r += rpi) {
        float v = y[(size_t)r * D + c]; s += v; q2 += v * v;
    }
    ss[tid] = s; sq[tid] = q2;
    __syncthreads();
    if (tid < D) {
        for (int o = 1; o < rpi; o++) { s += ss[tid + o*D]; q2 += sq[tid + o*D]; }
        part[(size_t)blockIdx.x * 2 * D + tid]     = s;
        part[(size_t)blockIdx.x * 2 * D + D + tid] = q2;
    }
}

__global__ void normalize_kernel(const float* __restrict__ y, const float* __restrict__ scale,
                                 const float* __restrict__ shift, int total, int D,
                                 float* __restrict__ out) {
    int i = blockIdx.x * 256 + threadIdx.x;
    if (i >= total) return;
    int c = i % D;
    out[i] = fmaxf(0.f, y[i] * scale[c] + shift[c]);
}

// ---------------- classifier head: single block, channel-per-thread ----------------
__global__ void classifier_kernel(const float* __restrict__ h4,
                                  const float* __restrict__ Wc1, const float* __restrict__ bc1,
                                  const float* __restrict__ gc1, const float* __restrict__ hc1,
                                  const float* __restrict__ Wc2, const float* __restrict__ bc2,
                                  const float* __restrict__ gc2, const float* __restrict__ hc2,
                                  const float* __restrict__ Wc3, const float* __restrict__ bc3,
                                  float* __restrict__ out) {
    __shared__ float sb[12288];
    float* z  = sb;
    float* z1 = sb + 8192;
    const int t = threadIdx.x;  // 256 threads
    for (int e = t; e < 8192; e += 256) {
        int b = e >> 9, c = e & 511;
        float s = 0.f;
        for (int k = 0; k < 16; k++) s += h4[((size_t)(b*16 + k))*512 + c];
        z[e] = s * (1.f/16.f);
    }
    __syncthreads();
    {
        float acc[16];
#pragma unroll
        for (int b = 0; b < 16; b++) acc[b] = bc1[t];
        for (int i = 0; i < 512; i++) {
            float w = Wc1[(size_t)i*256 + t];
#pragma unroll
            for (int b = 0; b < 16; b++) acc[b] += z[b*512 + i] * w;
        }
        float m = 0.f;
#pragma unroll
        for (int b = 0; b < 16; b++) m += acc[b];
        m *= (1.f/16.f);
        float v = 0.f;
#pragma unroll
        for (int b = 0; b < 16; b++) { float d = acc[b]-m; v += d*d; }
        v *= (1.f/16.f);
        float sc = gc1[t] * rsqrtf(v + BN_EPS);
        float sh = hc1[t] - m * sc;
#pragma unroll
        for (int b = 0; b < 16; b++) z1[b*256 + t] = fmaxf(0.f, acc[b]*sc + sh);
    }
    __syncthreads();
    float* z2 = sb;
    if (t < 128) {
        float acc[16];
#pragma unroll
        for (int b = 0; b < 16; b++) acc[b] = bc2[t];
        for (int i = 0; i < 256; i++) {
            float w = Wc2[(size_t)i*128 + t];
#pragma unroll
            for (int b = 0; b < 16; b++) acc[b] += z1[b*256 + i] * w;
        }
        float m = 0.f;
#pragma unroll
        for (int b = 0; b < 16; b++) m += acc[b];
        m *= (1.f/16.f);
        float v = 0.f;
#pragma unroll
        for (int b = 0; b < 16; b++) { float d = acc[b]-m; v += d*d; }
        v *= (1.f/16.f);
        float sc = gc2[t] * rsqrtf(v + BN_EPS);
        float sh = hc2[t] - m * sc;
#pragma unroll
        for (int b = 0; b < 16; b++) z2[b*128 + t] = fmaxf(0.f, acc[b]*sc + sh);
    }
    __syncthreads();
    if (t < 40) {
        float acc[16];
#pragma unroll
        for (int b = 0; b < 16; b++) acc[b] = bc3[t];
        for (int i = 0; i < 128; i++) {
            float w = Wc3[(size_t)i*40 + t];
#pragma unroll
            for (int b = 0; b < 16; b++) acc[b] += z2[b*128 + i] * w;
        }
#pragma unroll
        for (int b = 0; b < 16; b++) out[b*40 + t] = acc[b];
    }
}

// ---------------- driver ----------------
extern "C" void kernel_launch(void* const* d_in, const int* in_sizes, int n_in,
                              void* d_out, int out_size) {
    (void)in_sizes; (void)n_in; (void)out_size;
    const float* x   = (const float*)d_in[0];
    const float* W1  = (const float*)d_in[1];
    const float* g1  = (const float*)d_in[2];
    const float* b1  = (const float*)d_in[3];
    const float* W2  = (const float*)d_in[4];
    const float* g2  = (const float*)d_in[5];
    const float* b2  = (const float*)d_in[6];
    const float* W3  = (const float*)d_in[7];
    const float* g3  = (const float*)d_in[8];
    const float* b3  = (const float*)d_in[9];
    const float* W4  = (const float*)d_in[10];
    const float* g4  = (const float*)d_in[11];
    const float* b4  = (const float*)d_in[12];
    const float* W5  = (const float*)d_in[13];
    const float* g5  = (const float*)d_in[14];
    const float* b5  = (const float*)d_in[15];
    const float* Wc1 = (const float*)d_in[16];
    const float* bc1 = (const float*)d_in[17];
    const float* gc1 = (const float*)d_in[18];
    const float* hc1 = (const float*)d_in[19];
    const float* Wc2 = (const float*)d_in[20];
    const float* bc2 = (const float*)d_in[21];
    const float* gc2 = (const float*)d_in[22];
    const float* hc2 = (const float*)d_in[23];
    const float* Wc3 = (const float*)d_in[24];
    const float* bc3 = (const float*)d_in[25];
    float* out = (float*)d_out;

    float *ybuf, *h0, *p1, *h1, *p2, *h2, *p3, *h3, *p4, *h4, *part0, *scale, *shift;
    int* knn;
    cudaGetSymbolAddress((void**)&ybuf,  g_ybuf);
    cudaGetSymbolAddress((void**)&h0,    g_h0);
    cudaGetSymbolAddress((void**)&p1,    g_p1);
    cudaGetSymbolAddress((void**)&h1,    g_h1);
    cudaGetSymbolAddress((void**)&p2,    g_p2);
    cudaGetSymbolAddress((void**)&h2,    g_h2);
    cudaGetSymbolAddress((void**)&p3,    g_p3);
    cudaGetSymbolAddress((void**)&h3,    g_h3);
    cudaGetSymbolAddress((void**)&p4,    g_p4);
    cudaGetSymbolAddress((void**)&h4,    g_h4);
    cudaGetSymbolAddress((void**)&knn,   g_knn);
    cudaGetSymbolAddress((void**)&part0, g_part);
    cudaGetSymbolAddress((void**)&scale, g_scale);
    cudaGetSymbolAddress((void**)&shift, g_shift);

    // carve scratch from ybuf (temporally disjoint with stage0's use of ybuf[0..2M))
    float* ymax  = ybuf;                       // <= 1,048,576 floats
    float* ymin  = ybuf + 1048576;
    float* part  = ybuf + 2097152;             // <= 2,097,152 floats (TD1)
    float* part2 = ybuf + 4194304;             // <= 65,536 floats
    const int NR = 64;

    // ---- stage 0: h0 = relu(bn(x @ W1)) ----
    s0_gemm<<<(16*4096*32 + 255)/256, 256>>>(x, W1, ybuf);
    stats_partial<<<512, 256>>>(ybuf, 16*4096, 32, part0);
    stats_final<<<1, 32>>>(part0, 512, 32, (float)(16*4096), g1, b1, scale, shift);
    normalize_kernel<<<(16*4096*32 + 255)/256, 256>>>(ybuf, scale, shift, 16*4096*32, 32, h0);

    // ---- TD1: 4096 -> 1024, C=32 -> D=64 ----
    fps_kernel<4096, 512><<<16, 512>>>(x, 1024, p1);
    knn_kernel<<<16*1024, 128, 4096*4>>>(x, p1, 4096, 1024, knn);
    td_gemm_fused<<<16*1024, 64, 16*35*4>>>(x, h0, p1, knn, W2, 4096, 1024, 32, 64, ymax, ymin, part);
    stats_reduce<<<NR, 64>>>(part, 16*1024, 64, part2);
    stats_final<<<1, 64>>>(part2, NR, 64, (float)(16*1024*16), g2, b2, scale, shift);
    td_norm<<<(16*1024*64 + 255)/256, 256>>>(ymax, ymin, scale, shift, 16*1024*64, 64, h1);

    // ---- TD2: 1024 -> 256, C=64 -> D=128 ----
    fps_kernel<1024, 256><<<16, 256>>>(p1, 256, p2);
    knn_kernel<<<16*256, 128, 1024*4>>>(p1, p2, 1024, 256, knn);
    td_gemm_fused<<<16*256, 128, 16*67*4>>>(p1, h1, p2, knn, W3, 1024, 256, 64, 128, ymax, ymin, part);
    stats_reduce<<<NR, 128>>>(part, 16*256, 128, part2);
    stats_final<<<1, 128>>>(part2, NR, 128, (float)(16*256*16), g3, b3, scale, shift);
    td_norm<<<(16*256*128 + 255)/256, 256>>>(ymax, ymin, scale, shift, 16*256*128, 128, h2);

    // ---- TD3: 256 -> 64, C=128 -> D=256 ----
    fps_kernel<256, 256><<<16, 256>>>(p2, 64, p3);
    knn_kernel<<<16*64, 128, 256*4>>>(p2, p3, 256, 64, knn);
    td_gemm_fused<<<16*64, 256, 16*131*4>>>(p2, h2, p3, knn, W4, 256, 64, 128, 256, ymax, ymin, part);
    stats_reduce<<<NR, 256>>>(part, 16*64, 256, part2);
    stats_final<<<1, 256>>>(part2, NR, 256, (float)(16*64*16), g4, b4, scale, shift);
    td_norm<<<(16*64*256 + 255)/256, 256>>>(ymax, ymin, scale, shift, 16*64*256, 256, h3);

    // ---- TD4: 64 -> 16, C=256 -> D=512 ----
    fps_kernel<64, 64><<<16, 64>>>(p3, 16, p4);
    knn_kernel<<<16*16, 128, 64*4>>>(p3, p4, 64, 16, knn);
    td_gemm_fused<<<16*16, 512, 16*259*4>>>(p3, h3, p4, knn, W5, 64, 16, 256, 512, ymax, ymin, part);
    stats_reduce<<<NR, 512>>>(part, 16*16, 512, part2);
    stats_final<<<1, 512>>>(part2, NR, 512, (float)(16*16*16), g5, b5, scale, shift);
    td_norm<<<(16*16*512 + 255)/256, 256>>>(ymax, ymin, scale, shift, 16*16*512, 512, h4);

    // ---- classifier head ----
    classifier_kernel<<<1, 256>>>(h4, Wc1, bc1, gc1, hc1, Wc2, bc2, gc2, hc2, Wc3, bc3, out);
}

// round 11
// speedup vs baseline: 2.3944x; 1.0253x over previous
#include <cuda_runtime.h>
#include <math.h>

#define BN_EPS 1e-5f

// packed f32x2 helpers (sm_100+; only reachable via PTX; add/mul/fma only)
#define F32X2_PACK(o, lo, hi)  asm("mov.b64 %0, {%1, %2};" : "=l"(o) : "f"(lo), "f"(hi))
#define F32X2_UNPACK(lo, hi, i) asm("mov.b64 {%0, %1}, %2;" : "=f"(lo), "=f"(hi) : "l"(i))
#define F32X2_ADD(o, a, b)     asm("add.rn.f32x2 %0, %1, %2;" : "=l"(o) : "l"(a), "l"(b))
#define F32X2_MUL(o, a, b)     asm("mul.rn.f32x2 %0, %1, %2;" : "=l"(o) : "l"(a), "l"(b))
#define F32X2_FMA(o, a, b, c)  asm("fma.rn.f32x2 %0, %1, %2, %3;" : "=l"(o) : "l"(a), "l"(b), "l"(c))

// ---------------- scratch (static device globals; no allocations) ----------------
__device__ float g_ybuf[16*1024*16*64];   // carved: stage0 ybuf | ymax | ymin | part | part2
__device__ float g_h0[16*4096*32];
__device__ float g_p1[16*1024*3];
__device__ float g_h1[16*1024*64];
__device__ float g_p2[16*256*3];
__device__ float g_h2[16*256*128];
__device__ float g_p3[16*64*3];
__device__ float g_h3[16*64*256];
__device__ float g_p4[16*16*3];
__device__ float g_h4[16*16*512];
__device__ int   g_knn[16*1024*16];
__device__ float g_part[512*2*512];       // stage0 partials [NB][2][D]
__device__ float g_scale[512];
__device__ float g_shift[512];

// ---------------- side stream + fork/join events (created at load, before checkpoints) ----------------
struct GpuSync {
    cudaStream_t sb = nullptr;
    cudaEvent_t fork = nullptr, e1 = nullptr, e2 = nullptr, e3 = nullptr, e4 = nullptr;
    bool ok = false;
    GpuSync() {
        ok = (cudaStreamCreateWithFlags(&sb, cudaStreamNonBlocking) == cudaSuccess)
          && (cudaEventCreateWithFlags(&fork, cudaEventDisableTiming) == cudaSuccess)
          && (cudaEventCreateWithFlags(&e1,   cudaEventDisableTiming) == cudaSuccess)
          && (cudaEventCreateWithFlags(&e2,   cudaEventDisableTiming) == cudaSuccess)
          && (cudaEventCreateWithFlags(&e3,   cudaEventDisableTiming) == cudaSuccess)
          && (cudaEventCreateWithFlags(&e4,   cudaEventDisableTiming) == cudaSuccess);
    }
};
static GpuSync g_sync;

// ---------------- FPS (R9-proven): one block per batch, f32x2 distance loop ----------------
template<int N, int T>
__global__ void fps_kernel(const float* __restrict__ p, int M, float* __restrict__ newp) {
    constexpr int NPT = N / T;
    constexpr int NW  = T / 32;
    const int b = blockIdx.x, tid = threadIdx.x;
    const float* pb = p + (size_t)b * N * 3;
    __shared__ unsigned s_wd[16];
    __shared__ int      s_wi[16];
    __shared__ float    s_b[3];
    if (tid == 0) {
        s_b[0] = pb[0]; s_b[1] = pb[1]; s_b[2] = pb[2];
        float* o = newp + (size_t)b * M * 3;
        o[0] = pb[0]; o[1] = pb[1]; o[2] = pb[2];
    }
    __syncthreads();
    float bx = s_b[0], by = s_b[1], bz = s_b[2];

    if constexpr (NPT >= 2) {
        constexpr int NP2 = NPT / 2;
        unsigned long long px2[NP2], py2[NP2], pz2[NP2];
        float md[NPT];
#pragma unroll
        for (int a = 0; a < NP2; a++) {
            int g0 = (2*a)   * T + tid;
            int g1 = (2*a+1) * T + tid;
            F32X2_PACK(px2[a], pb[g0*3+0], pb[g1*3+0]);
            F32X2_PACK(py2[a], pb[g0*3+1], pb[g1*3+1]);
            F32X2_PACK(pz2[a], pb[g0*3+2], pb[g1*3+2]);
            md[2*a] = INFINITY; md[2*a+1] = INFINITY;
        }
        for (int t = 1; t < M; t++) {
            float nbx = -bx, nby = -by, nbz = -bz;
            unsigned long long nbx2, nby2, nbz2;
            F32X2_PACK(nbx2, nbx, nbx);
            F32X2_PACK(nby2, nby, nby);
            F32X2_PACK(nbz2, nbz, nbz);
            float best = 0.0f; int besti = 0x7fffffff;
#pragma unroll
            for (int a = 0; a < NP2; a++) {
                unsigned long long dx2, dy2, dz2, t2;
                F32X2_ADD(dx2, px2[a], nbx2);           // lx - bx (IEEE-identical to sub)
                F32X2_ADD(dy2, py2[a], nby2);
                F32X2_ADD(dz2, pz2[a], nbz2);
                F32X2_MUL(t2, dz2, dz2);                // dz*dz
                F32X2_FMA(t2, dy2, dy2, t2);            // dy*dy + .
                F32X2_FMA(t2, dx2, dx2, t2);            // dx*dx + .  (== R4 fmaf chain)
                float d0, d1;
                F32X2_UNPACK(d0, d1, t2);
                float v0 = fminf(md[2*a], d0);   md[2*a]   = v0;
                float v1 = fminf(md[2*a+1], d1); md[2*a+1] = v1;
                int g0 = (2*a)   * T + tid;
                int g1 = (2*a+1) * T + tid;
                if (v0 > best || (v0 == best && g0 < besti)) { best = v0; besti = g0; }
                if (v1 > best || (v1 == best && g1 < besti)) { best = v1; besti = g1; }
            }
            // warp argmax via REDUX (dists >= 0 so float bits are order-preserving)
            unsigned bb = __float_as_uint(best);
            unsigned mb = __reduce_max_sync(0xffffffffu, bb);
            int cand = (bb == mb) ? besti : 0x7fffffff;
            int wbi = __reduce_min_sync(0xffffffffu, cand);
            if ((tid & 31) == 0) { s_wd[tid >> 5] = mb; s_wi[tid >> 5] = wbi; }
            __syncthreads();
            if (tid < 32) {
                unsigned u = (tid < NW) ? s_wd[tid] : 0u;
                int      ii = (tid < NW) ? s_wi[tid] : 0x7fffffff;
                unsigned m2 = __reduce_max_sync(0xffffffffu, u);
                int c2 = (u == m2) ? ii : 0x7fffffff;
                int win = __reduce_min_sync(0xffffffffu, c2);
                if (tid == 0) {
                    const float* wp = pb + (size_t)win * 3;   // L1-hot
                    float cx = wp[0], cy = wp[1], cz = wp[2];
                    s_b[0] = cx; s_b[1] = cy; s_b[2] = cz;
                    float* o = newp + ((size_t)b * M + t) * 3;
                    o[0] = cx; o[1] = cy; o[2] = cz;
                }
            }
            __syncthreads();
            bx = s_b[0]; by = s_b[1]; bz = s_b[2];
        }
    } else {
        // scalar path (NPT == 1): identical to R4
        float lx = pb[tid*3+0], ly = pb[tid*3+1], lz = pb[tid*3+2], md = INFINITY;
        for (int t = 1; t < M; t++) {
            float best = 0.0f; int besti = 0x7fffffff;
            float dx = lx-bx, dy = ly-by, dz = lz-bz;
            float d = fmaf(dx, dx, fmaf(dy, dy, dz*dz));
            float v = fminf(md, d);
            md = v;
            if (v > best || (v == best && tid < besti)) { best = v; besti = tid; }
            unsigned bb = __float_as_uint(best);
            unsigned mb = __reduce_max_sync(0xffffffffu, bb);
            int cand = (bb == mb) ? besti : 0x7fffffff;
            int wbi = __reduce_min_sync(0xffffffffu, cand);
            if ((tid & 31) == 0) { s_wd[tid >> 5] = mb; s_wi[tid >> 5] = wbi; }
            __syncthreads();
            if (tid < 32) {
                unsigned u = (tid < NW) ? s_wd[tid] : 0u;
                int      ii = (tid < NW) ? s_wi[tid] : 0x7fffffff;
                unsigned m2 = __reduce_max_sync(0xffffffffu, u);
                int c2 = (u == m2) ? ii : 0x7fffffff;
                int win = __reduce_min_sync(0xffffffffu, c2);
                if (tid == 0) {
                    const float* wp = pb + (size_t)win * 3;
                    float cx = wp[0], cy = wp[1], cz = wp[2];
                    s_b[0] = cx; s_b[1] = cy; s_b[2] = cz;
                    float* o = newp + ((size_t)b * M + t) * 3;
                    o[0] = cx; o[1] = cy; o[2] = cz;
                }
            }
            __syncthreads();
            bx = s_b[0]; by = s_b[1]; bz = s_b[2];
        }
    }
}

// ---------------- kNN (R4-proven): 128 thr, cached per-thread minima, owner rescan ----------------
__global__ void knn_kernel(const float* __restrict__ p, const float* __restrict__ newp,
                           int N, int M, int* __restrict__ knn) {
    extern __shared__ float dist[];          // N floats
    __shared__ float s_tmin[128];
    __shared__ int   s_tidx[128];
    __shared__ int   s_win;
    const int q = blockIdx.x;
    const int b = q / M;
    const int tid = threadIdx.x;
    const float* pb = p + (size_t)b * N * 3;
    const float qx = newp[q*3+0], qy = newp[q*3+1], qz = newp[q*3+2];
    float bd = INFINITY; int bi = 0x7fffffff;
    for (int n = tid; n < N; n += 128) {
        float dx = qx - pb[n*3+0], dy = qy - pb[n*3+1], dz = qz - pb[n*3+2];
        float d = fmaf(dx, dx, fmaf(dy, dy, dz*dz));
        dist[n] = d;
        if (d < bd) { bd = d; bi = n; }      // ascending n -> first-index ties
    }
    s_tmin[tid] = bd; s_tidx[tid] = bi;
    __syncthreads();
    for (int r = 0; ; r++) {
        if (tid < 32) {
            float m0 = s_tmin[tid]; int i0 = s_tidx[tid];
#pragma unroll
            for (int off = 32; off < 128; off += 32) {
                float mm = s_tmin[tid + off]; int ii = s_tidx[tid + off];
                if (mm < m0 || (mm == m0 && ii < i0)) { m0 = mm; i0 = ii; }
            }
            unsigned b0 = __float_as_uint(m0);
            unsigned mb = __reduce_min_sync(0xffffffffu, b0);
            int cand = (b0 == mb) ? i0 : 0x7fffffff;
            int win = __reduce_min_sync(0xffffffffu, cand);
            if (tid == 0) { knn[(size_t)q*16 + r] = win; s_win = win; }
        }
        __syncthreads();
        if (r == 15) break;
        int win = s_win;
        if ((win & 127) == tid) {            // owner rescans its slice
            dist[win] = INFINITY;
            float nb = INFINITY; int ni = 0x7fffffff;
            for (int n = tid; n < N; n += 128) {
                float d = dist[n];
                if (d < nb) { nb = d; ni = n; }
            }
            s_tmin[tid] = nb; s_tidx[tid] = ni;
        }
        __syncthreads();
    }
}

// ---------------- fused grouped GEMM + max/min over k + per-block channel stats ----------------
__global__ void td_gemm_fused(const float* __restrict__ p, const float* __restrict__ h,
                              const float* __restrict__ newp, const int* __restrict__ knn,
                              const float* __restrict__ W, int N, int M, int C, int D,
                              float* __restrict__ ymax, float* __restrict__ ymin,
                              float* __restrict__ part) {
    extern __shared__ float feat[];          // 16*(C+3)
    __shared__ int   s_knn[16];
    __shared__ float s_np[3];
    const int q = blockIdx.x;
    const int b = q / M;
    const int t = threadIdx.x;               // D threads, one per output channel
    if (t < 16) s_knn[t] = knn[(size_t)q*16 + t];
    if (t < 3)  s_np[t]  = newp[q*3 + t];
    __syncthreads();
    const int F = C + 3;
    const float* pb = p + (size_t)b * N * 3;
    const float* hb = h + (size_t)b * N * C;
    for (int e = t; e < 16 * F; e += D) {
        int k = e / F, c = e - k * F;
        int n = s_knn[k];
        feat[e] = (c < 3) ? (pb[n*3 + c] - s_np[c]) : hb[(size_t)n * C + (c - 3)];
    }
    __syncthreads();
    float acc[16];
#pragma unroll
    for (int k = 0; k < 16; k++) acc[k] = 0.f;
#pragma unroll 2
    for (int c = 0; c < F; c++) {
        float w = W[(size_t)c * D + t];      // loaded once per c
#pragma unroll
        for (int k = 0; k < 16; k++) acc[k] += feat[k*F + c] * w;   // LDS broadcast
    }
    float mx = -INFINITY, mn = INFINITY, s = 0.f, s2 = 0.f;
#pragma unroll
    for (int k = 0; k < 16; k++) {
        float v = acc[k];
        mx = fmaxf(mx, v); mn = fminf(mn, v);
        s += v; s2 += v * v;
    }
    ymax[(size_t)q * D + t] = mx;
    ymin[(size_t)q * D + t] = mn;
    part[(size_t)q * 2 * D + t]     = s;
    part[(size_t)q * 2 * D + D + t] = s2;
}

// ---------------- stats tree: level-1 reduce of per-block partials ----------------
__global__ void stats_reduce(const float* __restrict__ part, int Q, int D,
                             float* __restrict__ out) {
    const int t = threadIdx.x;               // D threads
    const int per = (Q + gridDim.x - 1) / gridDim.x;
    const int r0 = blockIdx.x * per;
    const int r1 = min(r0 + per, Q);
    float s = 0.f, s2 = 0.f;
    for (int r = r0; r < r1; r++) {
        s  += part[(size_t)r * 2 * D + t];
        s2 += part[(size_t)r * 2 * D + D + t];
    }
    out[(size_t)blockIdx.x * 2 * D + t]     = s;
    out[(size_t)blockIdx.x * 2 * D + D + t] = s2;
}

__global__ void stats_final(const float* __restrict__ part, int NB, int D, float cnt,
                            const float* __restrict__ g, const float* __restrict__ bta,
                            float* __restrict__ scale, float* __restrict__ shift) {
    const int c = threadIdx.x;
    if (c >= D) return;
    float S = 0.f, Q2 = 0.f;
    for (int i = 0; i < NB; i++) {
        S  += part[(size_t)i * 2 * D + c];
        Q2 += part[(size_t)i * 2 * D + D + c];
    }
    float m = S / cnt;
    float v = Q2 / cnt - m * m;
    float sc = g[c] * rsqrtf(v + BN_EPS);
    scale[c] = sc;
    shift[c] = bta[c] - m * sc;
}

// ---------------- apply BN+ReLU to the sign-appropriate extremum ----------------
__global__ void td_norm(const float* __restrict__ ymax, const float* __restrict__ ymin,
                        const float* __restrict__ scale, const float* __restrict__ shift,
                        int total, int D, float* __restrict__ hout) {
    int i = blockIdx.x * 256 + threadIdx.x;
    if (i >= total) return;
    int d = i % D;
    float sc = scale[d];
    float v = (sc >= 0.f) ? ymax[i] : ymin[i];
    hout[i] = fmaxf(0.f, sc * v + shift[d]);
}

// ---------------- stage 0: h = p @ W1 (3->32) ----------------
__global__ void s0_gemm(const float* __restrict__ x, const float* __restrict__ W1,
                        float* __restrict__ y) {
    int i = blockIdx.x * 256 + threadIdx.x;
    if (i >= 16*4096*32) return;
    int pt = i >> 5, c = i & 31;
    const float* xp = x + (size_t)pt * 3;
    y[i] = xp[0]*W1[c] + xp[1]*W1[32+c] + xp[2]*W1[64+c];
}

__global__ void stats_partial(const float* __restrict__ y, int Q, int D, float* __restrict__ part) {
    const int NB = gridDim.x;
    const int rpb = (Q + NB - 1) / NB;
    const int r0 = blockIdx.x * rpb;
    const int r1 = min(r0 + rpb, Q);
    __shared__ float ss[256], sq[256];
    const int tid = threadIdx.x;
    const int rpi = 256 / D;
    const int c = tid % D;
    const int ro = tid / D;
    float s = 0.f, q2 = 0.f;
    for (int r = r0 + ro; r < r1; r += rpi) {
        float v = y[(size_t)r * D + c]; s += v; q2 += v * v;
    }
    ss[tid] = s; sq[tid] = q2;
    __syncthreads();
    if (tid < D) {
        for (int o = 1; o < rpi; o++) { s += ss[tid + o*D]; q2 += sq[tid + o*D]; }
        part[(size_t)blockIdx.x * 2 * D + tid]     = s;
        part[(size_t)blockIdx.x * 2 * D + D + tid] = q2;
    }
}

__global__ void normalize_kernel(const float* __restrict__ y, const float* __restrict__ scale,
                                 const float* __restrict__ shift, int total, int D,
                                 float* __restrict__ out) {
    int i = blockIdx.x * 256 + threadIdx.x;
    if (i >= total) return;
    int c = i % D;
    out[i] = fmaxf(0.f, y[i] * scale[c] + shift[c]);
}

// ---------------- classifier head: single block, channel-per-thread ----------------
__global__ void classifier_kernel(const float* __restrict__ h4,
                                  const float* __restrict__ Wc1, const float* __restrict__ bc1,
                                  const float* __restrict__ gc1, const float* __restrict__ hc1,
                                  const float* __restrict__ Wc2, const float* __restrict__ bc2,
                                  const float* __restrict__ gc2, const float* __restrict__ hc2,
                                  const float* __restrict__ Wc3, const float* __restrict__ bc3,
                                  float* __restrict__ out) {
    __shared__ float sb[12288];
    float* z  = sb;
    float* z1 = sb + 8192;
    const int t = threadIdx.x;  // 256 threads
    for (int e = t; e < 8192; e += 256) {
        int b = e >> 9, c = e & 511;
        float s = 0.f;
        for (int k = 0; k < 16; k++) s += h4[((size_t)(b*16 + k))*512 + c];
        z[e] = s * (1.f/16.f);
    }
    __syncthreads();
    {
        float acc[16];
#pragma unroll
        for (int b = 0; b < 16; b++) acc[b] = bc1[t];
        for (int i = 0; i < 512; i++) {
            float w = Wc1[(size_t)i*256 + t];
#pragma unroll
            for (int b = 0; b < 16; b++) acc[b] += z[b*512 + i] * w;
        }
        float m = 0.f;
#pragma unroll
        for (int b = 0; b < 16; b++) m += acc[b];
        m *= (1.f/16.f);
        float v = 0.f;
#pragma unroll
        for (int b = 0; b < 16; b++) { float d = acc[b]-m; v += d*d; }
        v *= (1.f/16.f);
        float sc = gc1[t] * rsqrtf(v + BN_EPS);
        float sh = hc1[t] - m * sc;
#pragma unroll
        for (int b = 0; b < 16; b++) z1[b*256 + t] = fmaxf(0.f, acc[b]*sc + sh);
    }
    __syncthreads();
    float* z2 = sb;
    if (t < 128) {
        float acc[16];
#pragma unroll
        for (int b = 0; b < 16; b++) acc[b] = bc2[t];
        for (int i = 0; i < 256; i++) {
            float w = Wc2[(size_t)i*128 + t];
#pragma unroll
            for (int b = 0; b < 16; b++) acc[b] += z1[b*256 + i] * w;
        }
        float m = 0.f;
#pragma unroll
        for (int b = 0; b < 16; b++) m += acc[b];
        m *= (1.f/16.f);
        float v = 0.f;
#pragma unroll
        for (int b = 0; b < 16; b++) { float d = acc[b]-m; v += d*d; }
        v *= (1.f/16.f);
        float sc = gc2[t] * rsqrtf(v + BN_EPS);
        float sh = hc2[t] - m * sc;
#pragma unroll
        for (int b = 0; b < 16; b++) z2[b*128 + t] = fmaxf(0.f, acc[b]*sc + sh);
    }
    __syncthreads();
    if (t < 40) {
        float acc[16];
#pragma unroll
        for (int b = 0; b < 16; b++) acc[b] = bc3[t];
        for (int i = 0; i < 128; i++) {
            float w = Wc3[(size_t)i*40 + t];
#pragma unroll
            for (int b = 0; b < 16; b++) acc[b] += z2[b*128 + i] * w;
        }
#pragma unroll
        for (int b = 0; b < 16; b++) out[b*40 + t] = acc[b];
    }
}

// ---------------- driver ----------------
extern "C" void kernel_launch(void* const* d_in, const int* in_sizes, int n_in,
                              void* d_out, int out_size) {
    (void)in_sizes; (void)n_in; (void)out_size;
    const float* x   = (const float*)d_in[0];
    const float* W1  = (const float*)d_in[1];
    const float* g1  = (const float*)d_in[2];
    const float* b1  = (const float*)d_in[3];
    const float* W2  = (const float*)d_in[4];
    const float* g2  = (const float*)d_in[5];
    const float* b2  = (const float*)d_in[6];
    const float* W3  = (const float*)d_in[7];
    const float* g3  = (const float*)d_in[8];
    const float* b3  = (const float*)d_in[9];
    const float* W4  = (const float*)d_in[10];
    const float* g4  = (const float*)d_in[11];
    const float* b4  = (const float*)d_in[12];
    const float* W5  = (const float*)d_in[13];
    const float* g5  = (const float*)d_in[14];
    const float* b5  = (const float*)d_in[15];
    const float* Wc1 = (const float*)d_in[16];
    const float* bc1 = (const float*)d_in[17];
    const float* gc1 = (const float*)d_in[18];
    const float* hc1 = (const float*)d_in[19];
    const float* Wc2 = (const float*)d_in[20];
    const float* bc2 = (const float*)d_in[21];
    const float* gc2 = (const float*)d_in[22];
    const float* hc2 = (const float*)d_in[23];
    const float* Wc3 = (const float*)d_in[24];
    const float* bc3 = (const float*)d_in[25];
    float* out = (float*)d_out;

    float *ybuf, *h0, *p1, *h1, *p2, *h2, *p3, *h3, *p4, *h4, *part0, *scale, *shift;
    int* knn;
    cudaGetSymbolAddress((void**)&ybuf,  g_ybuf);
    cudaGetSymbolAddress((void**)&h0,    g_h0);
    cudaGetSymbolAddress((void**)&p1,    g_p1);
    cudaGetSymbolAddress((void**)&h1,    g_h1);
    cudaGetSymbolAddress((void**)&p2,    g_p2);
    cudaGetSymbolAddress((void**)&h2,    g_h2);
    cudaGetSymbolAddress((void**)&p3,    g_p3);
    cudaGetSymbolAddress((void**)&h3,    g_h3);
    cudaGetSymbolAddress((void**)&p4,    g_p4);
    cudaGetSymbolAddress((void**)&h4,    g_h4);
    cudaGetSymbolAddress((void**)&knn,   g_knn);
    cudaGetSymbolAddress((void**)&part0, g_part);
    cudaGetSymbolAddress((void**)&scale, g_scale);
    cudaGetSymbolAddress((void**)&shift, g_shift);

    // carve scratch from ybuf (temporally disjoint with stage0's use of ybuf[0..2M))
    float* ymax  = ybuf;                       // <= 1,048,576 floats
    float* ymin  = ybuf + 1048576;
    float* part  = ybuf + 2097152;             // <= 2,097,152 floats (TD1)
    float* part2 = ybuf + 4194304;             // <= 65,536 floats
    const int NR = 64;

    const bool ov = g_sync.ok;
    cudaStream_t SB = ov ? g_sync.sb : 0;

    // ---- fork: FPS chain on side stream (positions only; independent of features) ----
    if (ov) { cudaEventRecord(g_sync.fork, 0); cudaStreamWaitEvent(SB, g_sync.fork, 0); }
    fps_kernel<4096, 512><<<16, 512, 0, SB>>>(x, 1024, p1);
    if (ov) cudaEventRecord(g_sync.e1, SB);
    fps_kernel<1024, 256><<<16, 256, 0, SB>>>(p1, 256, p2);
    if (ov) cudaEventRecord(g_sync.e2, SB);
    fps_kernel<256, 256><<<16, 256, 0, SB>>>(p2, 64, p3);
    if (ov) cudaEventRecord(g_sync.e3, SB);
    fps_kernel<64, 64><<<16, 64, 0, SB>>>(p3, 16, p4);
    if (ov) cudaEventRecord(g_sync.e4, SB);

    // ---- main stream: stage 0 (overlaps fps1) ----
    s0_gemm<<<(16*4096*32 + 255)/256, 256>>>(x, W1, ybuf);
    stats_partial<<<512, 256>>>(ybuf, 16*4096, 32, part0);
    stats_final<<<1, 32>>>(part0, 512, 32, (float)(16*4096), g1, b1, scale, shift);
    normalize_kernel<<<(16*4096*32 + 255)/256, 256>>>(ybuf, scale, shift, 16*4096*32, 32, h0);

    // ---- TD1: 4096 -> 1024, C=32 -> D=64 ----
    if (ov) cudaStreamWaitEvent(0, g_sync.e1, 0);
    knn_kernel<<<16*1024, 128, 4096*4>>>(x, p1, 4096, 1024, knn);
    td_gemm_fused<<<16*1024, 64, 16*35*4>>>(x, h0, p1, knn, W2, 4096, 1024, 32, 64, ymax, ymin, part);
    stats_reduce<<<NR, 64>>>(part, 16*1024, 64, part2);
    stats_final<<<1, 64>>>(part2, NR, 64, (float)(16*1024*16), g2, b2, scale, shift);
    td_norm<<<(16*1024*64 + 255)/256, 256>>>(ymax, ymin, scale, shift, 16*1024*64, 64, h1);

    // ---- TD2: 1024 -> 256, C=64 -> D=128 ----
    if (ov) cudaStreamWaitEvent(0, g_sync.e2, 0);
    knn_kernel<<<16*256, 128, 1024*4>>>(p1, p2, 1024, 256, knn);
    td_gemm_fused<<<16*256, 128, 16*67*4>>>(p1, h1, p2, knn, W3, 1024, 256, 64, 128, ymax, ymin, part);
    stats_reduce<<<NR, 128>>>(part, 16*256, 128, part2);
    stats_final<<<1, 128>>>(part2, NR, 128, (float)(16*256*16), g3, b3, scale, shift);
    td_norm<<<(16*256*128 + 255)/256, 256>>>(ymax, ymin, scale, shift, 16*256*128, 128, h2);

    // ---- TD3: 256 -> 64, C=128 -> D=256 ----
    if (ov) cudaStreamWaitEvent(0, g_sync.e3, 0);
    knn_kernel<<<16*64, 128, 256*4>>>(p2, p3, 256, 64, knn);
    td_gemm_fused<<<16*64, 256, 16*131*4>>>(p2, h2, p3, knn, W4, 256, 64, 128, 256, ymax, ymin, part);
    stats_reduce<<<NR, 256>>>(part, 16*64, 256, part2);
    stats_final<<<1, 256>>>(part2, NR, 256, (float)(16*64*16), g4, b4, scale, shift);
    td_norm<<<(16*64*256 + 255)/256, 256>>>(ymax, ymin, scale, shift, 16*64*256, 256, h3);

    // ---- TD4: 64 -> 16, C=256 -> D=512 (join: waits last side-stream event) ----
    if (ov) cudaStreamWaitEvent(0, g_sync.e4, 0);
    knn_kernel<<<16*16, 128, 64*4>>>(p3, p4, 64, 16, knn);
    td_gemm_fused<<<16*16, 512, 16*259*4>>>(p3, h3, p4, knn, W5, 64, 16, 256, 512, ymax, ymin, part);
    stats_reduce<<<NR, 512>>>(part, 16*16, 512, part2);
    stats_final<<<1, 512>>>(part2, NR, 512, (float)(16*16*16), g5, b5, scale, shift);
    td_norm<<<(16*16*512 + 255)/256, 256>>>(ymax, ymin, scale, shift, 16*16*512, 512, h4);

    // ---- classifier head ----
    classifier_kernel<<<1, 256>>>(h4, Wc1, bc1, gc1, hc1, Wc2, bc2, gc2, hc2, Wc3, bc3, out);
}